// round 14
// baseline (speedup 1.0000x reference)
#include <cuda_runtime.h>
#include <cuda_bf16.h>
#include <cuda_fp16.h>
#include <math.h>
#include <stdint.h>

#define EMB 768
#define HEADS 12
#define HD 64
#define SEQ 4096
#define QKV_LD (3 * EMB)   // 2304
#define LIMB ((size_t)HEADS * SEQ * HD)   // halves per K/V limb plane
#define LOG2E 1.4426950408889634f
#define NSPLIT_K 3

// Scratch (static device globals — no allocation)
__device__ __align__(16) float g_qkv[(size_t)SEQ * QKV_LD];        // Q|K|V fp32
__device__ __align__(16) __half g_k16[2 * HEADS * SEQ * HD];       // [limb][h][k][d]
__device__ __align__(16) __half g_v16[2 * HEADS * SEQ * HD];       // [limb][h][c][k]
__device__ __align__(16) float g_part[(size_t)NSPLIT_K * SEQ * EMB];
__device__ __align__(16) float g_ml[(size_t)NSPLIT_K * HEADS * SEQ * 2];
// Pre-split bf16 limb planes for projection GEMMs
__device__ __align__(16) __nv_bfloat16 g_x16[3 * (size_t)SEQ * EMB];
__device__ __align__(16) __nv_bfloat16 g_w316[3 * (size_t)QKV_LD * EMB];
__device__ __align__(16) __nv_bfloat16 g_w216[2 * (size_t)EMB * EMB];
__device__ __align__(16) __nv_bfloat16 g_ctx16[2 * (size_t)SEQ * EMB];

// ---------------------------------------------------------------------------
// HMMA helpers (mma.sync — supported on base sm_103 target)
// ---------------------------------------------------------------------------
__device__ __forceinline__ void mma_bf16(float* d, const uint32_t* a, const uint32_t* b) {
    asm volatile(
        "mma.sync.aligned.m16n8k16.row.col.f32.bf16.bf16.f32 "
        "{%0,%1,%2,%3}, {%4,%5,%6,%7}, {%8,%9}, {%0,%1,%2,%3};"
        : "+f"(d[0]), "+f"(d[1]), "+f"(d[2]), "+f"(d[3])
        : "r"(a[0]), "r"(a[1]), "r"(a[2]), "r"(a[3]), "r"(b[0]), "r"(b[1]));
}
__device__ __forceinline__ void mma_f16(float* d, const uint32_t* a, const uint32_t* b) {
    asm volatile(
        "mma.sync.aligned.m16n8k16.row.col.f32.f16.f16.f32 "
        "{%0,%1,%2,%3}, {%4,%5,%6,%7}, {%8,%9}, {%0,%1,%2,%3};"
        : "+f"(d[0]), "+f"(d[1]), "+f"(d[2]), "+f"(d[3])
        : "r"(a[0]), "r"(a[1]), "r"(a[2]), "r"(a[3]), "r"(b[0]), "r"(b[1]));
}
__device__ __forceinline__ uint32_t h2bits(__half2 h) { return *(uint32_t*)&h; }
__device__ __forceinline__ float ex2f(float x) {
    float r; asm("ex2.approx.ftz.f32 %0, %1;" : "=f"(r) : "f"(x)); return r;
}

// fp32 pair -> fp16 hi/lo limbs (packed f16x2: x -> low half)
__device__ __forceinline__ void split_h2(float x, float y, uint32_t& hi, uint32_t& lo) {
    __half2 h = __floats2half2_rn(x, y);
    float2 f = __half22float2(h);
    __half2 l = __floats2half2_rn(x - f.x, y - f.y);
    hi = h2bits(h);
    lo = h2bits(l);
}

// fp32 pair -> bf16 limb split
__device__ __forceinline__ void split_pair_bf(
    float x, float y, uint32_t& h, uint32_t& m, uint32_t& l, bool want3)
{
    __nv_bfloat162 hb = __float22bfloat162_rn(make_float2(x, y));
    float2 hf = __bfloat1622float2(hb);
    float rx = x - hf.x, ry = y - hf.y;
    __nv_bfloat162 mb = __float22bfloat162_rn(make_float2(rx, ry));
    h = *(uint32_t*)&hb;
    m = *(uint32_t*)&mb;
    if (want3) {
        float2 mf = __bfloat1622float2(mb);
        __nv_bfloat162 lb = __float22bfloat162_rn(make_float2(rx - mf.x, ry - mf.y));
        l = *(uint32_t*)&lb;
    } else {
        l = 0;
    }
}

// ---------------------------------------------------------------------------
// Prep: fp32 array -> NS bf16 limb planes (plane stride n elements).
// One thread = 8 elements.
// ---------------------------------------------------------------------------
template<int NS>
__global__ __launch_bounds__(256) void split_bf_kernel(
    const float* __restrict__ src, __nv_bfloat16* __restrict__ dst, size_t n)
{
    const size_t i = ((size_t)blockIdx.x * 256 + threadIdx.x) * 8;
    float4 v0 = *(const float4*)(src + i);
    float4 v1 = *(const float4*)(src + i + 4);
    uint32_t h[4], m[4], l[4];
    split_pair_bf(v0.x, v0.y, h[0], m[0], l[0], NS == 3);
    split_pair_bf(v0.z, v0.w, h[1], m[1], l[1], NS == 3);
    split_pair_bf(v1.x, v1.y, h[2], m[2], l[2], NS == 3);
    split_pair_bf(v1.z, v1.w, h[3], m[3], l[3], NS == 3);
    *(uint4*)(dst + i)         = make_uint4(h[0], h[1], h[2], h[3]);
    *(uint4*)(dst + n + i)     = make_uint4(m[0], m[1], m[2], m[3]);
    if (NS == 3)
        *(uint4*)(dst + 2 * n + i) = make_uint4(l[0], l[1], l[2], l[3]);
}

// ---------------------------------------------------------------------------
// HMMA GEMM on PRE-SPLIT bf16 limbs: C = A @ B^T (+bias).
// A/B given as NSPLIT limb planes (stride sA/sB). Fill is pure LDG/STS.
// 128x128 tile, BK=32, 256 threads, 2 CTAs/SM.
// ---------------------------------------------------------------------------
#define LT (128 * 40)   // bf16 elements per limb tile

template<int NSPLIT>
__global__ __launch_bounds__(256, 2) void hmma_gemm_pre(
    const __nv_bfloat16* __restrict__ A, size_t sA,
    const __nv_bfloat16* __restrict__ B, size_t sB,
    const float* __restrict__ bias, float* __restrict__ C,
    int M, int N, int K)
{
    extern __shared__ __align__(16) char smem[];
    __nv_bfloat16* As = (__nv_bfloat16*)smem;
    __nv_bfloat16* Bs = As + NSPLIT * LT;

    const int tid  = threadIdx.x;
    const int lane = tid & 31;
    const int wid  = tid >> 5;
    const int wm   = wid >> 2;
    const int wn   = wid & 3;
    const int grp  = lane >> 2;
    const int tg   = lane & 3;
    const int bm0  = blockIdx.y * 128;
    const int bn0  = blockIdx.x * 128;

    float d[4][4][4];
#pragma unroll
    for (int am = 0; am < 4; am++)
#pragma unroll
        for (int an = 0; an < 4; an++)
#pragma unroll
            for (int r = 0; r < 4; r++) d[am][an][r] = 0.0f;

    const int NPR = (NSPLIT == 3) ? 6 : 3;
    const int PA[6] = {0, 0, 1, 0, 2, 1};
    const int PB[6] = {0, 1, 0, 2, 0, 1};

    for (int k0 = 0; k0 < K; k0 += 32) {
        __syncthreads();
#pragma unroll
        for (int half = 0; half < 2; half++) {
            const __nv_bfloat16* src = half ? (B + (size_t)bn0 * K) : (A + (size_t)bm0 * K);
            const size_t ps = half ? sB : sA;
            __nv_bfloat16* dst = half ? Bs : As;
#pragma unroll
            for (int it = 0; it < 2; it++) {
                const int f   = tid + it * 256;
                const int row = f >> 2;
                const int c8  = f & 3;
                const size_t go = (size_t)row * K + k0 + c8 * 8;
                const int   so = row * 40 + c8 * 8;
#pragma unroll
                for (int lb = 0; lb < NSPLIT; lb++) {
                    uint4 v = *(const uint4*)(src + lb * ps + go);
                    *(uint4*)&dst[lb * LT + so] = v;
                }
            }
        }
        __syncthreads();

#pragma unroll
        for (int ks = 0; ks < 2; ks++) {
#pragma unroll
            for (int p = 0; p < NPR; p++) {
                const int la = PA[p], lb = PB[p];
                uint32_t afr[4][4];
#pragma unroll
                for (int am = 0; am < 4; am++) {
                    const __nv_bfloat16* ap =
                        As + la * LT + (wm * 64 + am * 16 + grp) * 40 + ks * 16 + tg * 2;
                    afr[am][0] = *(const uint32_t*)ap;
                    afr[am][1] = *(const uint32_t*)(ap + 8 * 40);
                    afr[am][2] = *(const uint32_t*)(ap + 8);
                    afr[am][3] = *(const uint32_t*)(ap + 8 * 40 + 8);
                }
#pragma unroll
                for (int an = 0; an < 4; an++) {
                    const __nv_bfloat16* bp =
                        Bs + lb * LT + (wn * 32 + an * 8 + grp) * 40 + ks * 16 + tg * 2;
                    uint32_t bfr[2];
                    bfr[0] = *(const uint32_t*)bp;
                    bfr[1] = *(const uint32_t*)(bp + 8);
#pragma unroll
                    for (int am = 0; am < 4; am++)
                        mma_bf16(d[am][an], afr[am], bfr);
                }
            }
        }
    }

#pragma unroll
    for (int am = 0; am < 4; am++) {
        const int r0 = bm0 + wm * 64 + am * 16 + grp;
#pragma unroll
        for (int an = 0; an < 4; an++) {
            const int c0 = bn0 + wn * 32 + an * 8 + tg * 2;
            float bv0 = 0.0f, bv1 = 0.0f;
            if (bias) { bv0 = bias[c0]; bv1 = bias[c0 + 1]; }
            *(float2*)&C[(size_t)r0 * N + c0] =
                make_float2(d[am][an][0] + bv0, d[am][an][1] + bv1);
            *(float2*)&C[(size_t)(r0 + 8) * N + c0] =
                make_float2(d[am][an][2] + bv0, d[am][an][3] + bv1);
        }
    }
}

// ---------------------------------------------------------------------------
// Prep K: fp32 -> fp16 hi/lo limbs, layout [limb][h][k][d]. (proven)
// ---------------------------------------------------------------------------
__global__ __launch_bounds__(256) void prep_k(
    const float* __restrict__ qkv, __half* __restrict__ k16)
{
    const int u  = blockIdx.x * 256 + threadIdx.x;
    const int hk = u >> 2, ch = u & 3;
    const int h = hk >> 12, k = hk & 4095;
    const float* src = qkv + (size_t)k * QKV_LD + EMB + h * HD + ch * 16;
    __half* dh = k16 + ((size_t)h * SEQ + k) * HD + ch * 16;

    uint32_t hi[8], lo[8];
#pragma unroll
    for (int j = 0; j < 4; j++) {
        float4 v = *(const float4*)(src + j * 4);
        split_h2(v.x, v.y, hi[j * 2], lo[j * 2]);
        split_h2(v.z, v.w, hi[j * 2 + 1], lo[j * 2 + 1]);
    }
    *(uint4*)dh       = make_uint4(hi[0], hi[1], hi[2], hi[3]);
    *(uint4*)(dh + 8) = make_uint4(hi[4], hi[5], hi[6], hi[7]);
    __half* dl = dh + LIMB;
    *(uint4*)dl       = make_uint4(lo[0], lo[1], lo[2], lo[3]);
    *(uint4*)(dl + 8) = make_uint4(lo[4], lo[5], lo[6], lo[7]);
}

// ---------------------------------------------------------------------------
// Prep V: split + transpose to [limb][h][c][k]. (proven)
// ---------------------------------------------------------------------------
__global__ __launch_bounds__(256) void prep_v(
    const float* __restrict__ qkv, __half* __restrict__ v16)
{
    __shared__ __align__(16) __half sv[2][64][80];
    const int h  = blockIdx.y, kb = blockIdx.x;
    const int t  = threadIdx.x;
    {
        const int k = t >> 2, ch = t & 3;
        const float* src = qkv + (size_t)(kb * 64 + k) * QKV_LD + 2 * EMB + h * HD + ch * 16;
#pragma unroll
        for (int j = 0; j < 16; j += 2) {
            float2 v = *(const float2*)(src + j);
            __half2 a = __floats2half2_rn(v.x, v.y);
            float2 f = __half22float2(a);
            __half2 r = __floats2half2_rn(v.x - f.x, v.y - f.y);
            const int c = ch * 16 + j;
            sv[0][c][k]     = __low2half(a);
            sv[0][c + 1][k] = __high2half(a);
            sv[1][c][k]     = __low2half(r);
            sv[1][c + 1][k] = __high2half(r);
        }
    }
    __syncthreads();
    {
        const int c = t >> 2, kc = t & 3;
        __half* dst = v16 + ((size_t)h * HD + c) * SEQ + kb * 64 + kc * 16;
#pragma unroll
        for (int j = 0; j < 2; j++) {
            *(uint4*)(dst + j * 8)        = *(const uint4*)&sv[0][c][kc * 16 + j * 8];
            *(uint4*)(dst + LIMB + j * 8) = *(const uint4*)&sv[1][c][kc * 16 + j * 8];
        }
    }
}

// ---------------------------------------------------------------------------
// HMMA flash attention, split-K x3, REGISTER-RESIDENT P:
// the S C-fragment is re-packed in registers as the PV A-fragment,
// eliminating the P SMEM tile and its store/load traffic.
// ---------------------------------------------------------------------------
#define SQH 0                    // Q hi  [128][72]
#define SQL (SQH + 128 * 72)     // Q lo
#define SKH (SQL + 128 * 72)     // K hi  [64 key][72 d]
#define SKL (SKH + 64 * 72)      // K lo
#define SVH (SKL + 64 * 72)      // V^T hi [64 c][72 k]
#define SVL (SVH + 64 * 72)      // V^T lo
#define ATTN_HALVES (SVL + 64 * 72)           // 36864
#define ATTN_SMEM_BYTES (ATTN_HALVES * 2)     // 73728

__global__ __launch_bounds__(256, 2) void attn_hmma(
    const float* __restrict__ qkv,
    const __half* __restrict__ k16, const __half* __restrict__ v16,
    float* __restrict__ opart, float* __restrict__ ml)
{
    extern __shared__ __align__(16) __half sh[];
    const int tid  = threadIdx.x;
    const int lane = tid & 31;
    const int wid  = tid >> 5;
    const int grp  = lane >> 2;
    const int tg   = lane & 3;
    const int h    = blockIdx.y;
    const int q0   = blockIdx.x * 128;
    const int sp   = blockIdx.z;

    const int kt0 = (sp == 0) ? 0 : (sp == 1 ? 22 : 43);
    const int kt1 = (sp == 0) ? 22 : (sp == 1 ? 43 : 64);

    // ---- Load Q tile, scale by 8*log2e, split into fp16 limbs ----
#pragma unroll
    for (int f = tid; f < 512; f += 256) {
        const int row = f >> 2, ch = f & 3;
        const float* p = qkv + (size_t)(q0 + row) * QKV_LD + h * HD + ch * 16;
        uint32_t hi[8], lo[8];
#pragma unroll
        for (int j = 0; j < 4; j++) {
            float4 v = *(const float4*)(p + j * 4);
            const float sc = 8.0f * LOG2E;
            split_h2(v.x * sc, v.y * sc, hi[j * 2], lo[j * 2]);
            split_h2(v.z * sc, v.w * sc, hi[j * 2 + 1], lo[j * 2 + 1]);
        }
        const int o = row * 72 + ch * 16;
        *(uint4*)&sh[SQH + o]     = make_uint4(hi[0], hi[1], hi[2], hi[3]);
        *(uint4*)&sh[SQH + o + 8] = make_uint4(hi[4], hi[5], hi[6], hi[7]);
        *(uint4*)&sh[SQL + o]     = make_uint4(lo[0], lo[1], lo[2], lo[3]);
        *(uint4*)&sh[SQL + o + 8] = make_uint4(lo[4], lo[5], lo[6], lo[7]);
    }

    const __half* kP = k16 + (size_t)h * SEQ * HD;
    const __half* vP = v16 + (size_t)h * HD * SEQ;

    int clt[4], crow[4], cseg[4];
#pragma unroll
    for (int i = 0; i < 4; i++) {
        const int g = tid + i * 256;
        clt[i]  = g >> 9;
        crow[i] = (g >> 3) & 63;
        cseg[i] = g & 7;
    }

    auto sts_chunk = [&](int base_h, int base_l, int i, uint4 v) {
        const int off = (base_h + (clt[i] ? (base_l - base_h) : 0))
                        + crow[i] * 72 + cseg[i] * 8;
        *(uint2*)&sh[off]     = make_uint2(v.x, v.y);
        *(uint2*)&sh[off + 4] = make_uint2(v.z, v.w);
    };

    // ---- Preload K(kt0) and V(kt0) ----
    {
        uint4 kc4[4], vc4[4];
#pragma unroll
        for (int i = 0; i < 4; i++) {
            kc4[i] = *(const uint4*)(kP + clt[i] * LIMB
                         + (size_t)(kt0 * 64 + crow[i]) * HD + cseg[i] * 8);
            vc4[i] = *(const uint4*)(vP + clt[i] * LIMB
                         + (size_t)crow[i] * SEQ + kt0 * 64 + cseg[i] * 8);
        }
#pragma unroll
        for (int i = 0; i < 4; i++) {
            sts_chunk(SKH, SKL, i, kc4[i]);
            sts_chunk(SVH, SVL, i, vc4[i]);
        }
    }
    __syncthreads();

    float m0 = -1e30f, m1 = -1e30f, l0 = 0.0f, l1 = 0.0f;
    float O[8][4];
#pragma unroll
    for (int nt = 0; nt < 8; nt++)
#pragma unroll
        for (int r = 0; r < 4; r++) O[nt][r] = 0.0f;

    const int qrow = (wid * 16 + grp) * 72 + tg * 2;

    for (int it = kt0; it < kt1; it++) {
        const int kt = it * 64;
        const bool pf = (it + 1) < kt1;

        // Prefetch K(it+1), V(it+1) (hidden under S-MMA + softmax + PV)
        uint4 kc4[4], vc4[4];
        if (pf) {
#pragma unroll
            for (int i = 0; i < 4; i++) {
                kc4[i] = *(const uint4*)(kP + clt[i] * LIMB
                             + (size_t)(kt + 64 + crow[i]) * HD + cseg[i] * 8);
                vc4[i] = *(const uint4*)(vP + clt[i] * LIMB
                             + (size_t)crow[i] * SEQ + kt + 64 + cseg[i] * 8);
            }
        }

        // ---- S = Q K^T (3 fp16 limb products) ----
        float s[8][4];
#pragma unroll
        for (int nt = 0; nt < 8; nt++)
#pragma unroll
            for (int r = 0; r < 4; r++) s[nt][r] = 0.0f;

#pragma unroll
        for (int ks = 0; ks < 4; ks++) {
            const int qa = qrow + ks * 16;
            uint32_t ah[4], al_[4];
            ah[0] = *(const uint32_t*)&sh[SQH + qa];
            ah[1] = *(const uint32_t*)&sh[SQH + qa + 8 * 72];
            ah[2] = *(const uint32_t*)&sh[SQH + qa + 8];
            ah[3] = *(const uint32_t*)&sh[SQH + qa + 8 * 72 + 8];
            al_[0] = *(const uint32_t*)&sh[SQL + qa];
            al_[1] = *(const uint32_t*)&sh[SQL + qa + 8 * 72];
            al_[2] = *(const uint32_t*)&sh[SQL + qa + 8];
            al_[3] = *(const uint32_t*)&sh[SQL + qa + 8 * 72 + 8];
#pragma unroll
            for (int nt = 0; nt < 8; nt++) {
                const int ka = (nt * 8 + grp) * 72 + ks * 16 + tg * 2;
                uint32_t kh[2], kl[2];
                kh[0] = *(const uint32_t*)&sh[SKH + ka];
                kh[1] = *(const uint32_t*)&sh[SKH + ka + 8];
                kl[0] = *(const uint32_t*)&sh[SKL + ka];
                kl[1] = *(const uint32_t*)&sh[SKL + ka + 8];
                mma_f16(s[nt], ah, kh);
                mma_f16(s[nt], al_, kh);
                mma_f16(s[nt], ah, kl);
            }
        }

        // ---- Online softmax (log2 domain) ----
        float mx0 = -1e30f, mx1 = -1e30f;
#pragma unroll
        for (int nt = 0; nt < 8; nt++) {
            mx0 = fmaxf(mx0, fmaxf(s[nt][0], s[nt][1]));
            mx1 = fmaxf(mx1, fmaxf(s[nt][2], s[nt][3]));
        }
        mx0 = fmaxf(mx0, __shfl_xor_sync(0xffffffffu, mx0, 1));
        mx0 = fmaxf(mx0, __shfl_xor_sync(0xffffffffu, mx0, 2));
        mx1 = fmaxf(mx1, __shfl_xor_sync(0xffffffffu, mx1, 1));
        mx1 = fmaxf(mx1, __shfl_xor_sync(0xffffffffu, mx1, 2));

        const float mn0 = fmaxf(m0, mx0), mn1 = fmaxf(m1, mx1);
        const float al0 = ex2f(m0 - mn0), al1 = ex2f(m1 - mn1);
        m0 = mn0; m1 = mn1;

        float sum0 = 0.0f, sum1 = 0.0f;
#pragma unroll
        for (int nt = 0; nt < 8; nt++) {
            s[nt][0] = ex2f(s[nt][0] - mn0); sum0 += s[nt][0];
            s[nt][1] = ex2f(s[nt][1] - mn0); sum0 += s[nt][1];
            s[nt][2] = ex2f(s[nt][2] - mn1); sum1 += s[nt][2];
            s[nt][3] = ex2f(s[nt][3] - mn1); sum1 += s[nt][3];
        }
        sum0 += __shfl_xor_sync(0xffffffffu, sum0, 1);
        sum0 += __shfl_xor_sync(0xffffffffu, sum0, 2);
        sum1 += __shfl_xor_sync(0xffffffffu, sum1, 1);
        sum1 += __shfl_xor_sync(0xffffffffu, sum1, 2);
        l0 = l0 * al0 + sum0;
        l1 = l1 * al1 + sum1;

#pragma unroll
        for (int nt = 0; nt < 8; nt++) {
            O[nt][0] *= al0; O[nt][1] *= al0;
            O[nt][2] *= al1; O[nt][3] *= al1;
        }

        // ---- O += P V: P packed from S fragments IN REGISTERS ----
        // C-frag(S tiles 2kc,2kc+1) == A-frag(P, k-chunk kc) identity.
#pragma unroll
        for (int kc = 0; kc < 4; kc++) {
            uint32_t ph[4], pl[4];
            split_h2(s[2 * kc][0],     s[2 * kc][1],     ph[0], pl[0]);
            split_h2(s[2 * kc][2],     s[2 * kc][3],     ph[1], pl[1]);
            split_h2(s[2 * kc + 1][0], s[2 * kc + 1][1], ph[2], pl[2]);
            split_h2(s[2 * kc + 1][2], s[2 * kc + 1][3], ph[3], pl[3]);
#pragma unroll
            for (int nt = 0; nt < 8; nt++) {
                const int va = (nt * 8 + grp) * 72 + kc * 16 + tg * 2;
                uint32_t vh[2], vl[2];
                vh[0] = *(const uint32_t*)&sh[SVH + va];
                vh[1] = *(const uint32_t*)&sh[SVH + va + 8];
                vl[0] = *(const uint32_t*)&sh[SVL + va];
                vl[1] = *(const uint32_t*)&sh[SVL + va + 8];
                mma_f16(O[nt], ph, vh);
                mma_f16(O[nt], pl, vh);
                mma_f16(O[nt], ph, vl);
            }
        }

        if (pf) {
            __syncthreads();   // all K(it)/V(it) smem reads done
#pragma unroll
            for (int i = 0; i < 4; i++) {
                sts_chunk(SKH, SKL, i, kc4[i]);
                sts_chunk(SVH, SVL, i, vc4[i]);
            }
            __syncthreads();   // K(it+1), V(it+1) visible
        }
    }

    // ---- Write UNNORMALIZED partial O + (m,l) per row ----
    const int r0 = q0 + wid * 16 + grp;
    float* op = opart + (size_t)sp * SEQ * EMB;
#pragma unroll
    for (int nt = 0; nt < 8; nt++) {
        const int c = h * HD + nt * 8 + tg * 2;
        *(float2*)&op[(size_t)r0 * EMB + c]       = make_float2(O[nt][0], O[nt][1]);
        *(float2*)&op[(size_t)(r0 + 8) * EMB + c] = make_float2(O[nt][2], O[nt][3]);
    }
    if (tg == 0) {
        float* mlp = ml + (((size_t)sp * HEADS + h) * SEQ) * 2;
        *(float2*)&mlp[(size_t)r0 * 2]       = make_float2(m0, l0);
        *(float2*)&mlp[(size_t)(r0 + 8) * 2] = make_float2(m1, l1);
    }
}

// ---------------------------------------------------------------------------
// Merge the 3 split-K partials and emit ctx directly as 2 bf16 limb planes.
// ---------------------------------------------------------------------------
__global__ __launch_bounds__(256) void merge_kernel(
    const float* __restrict__ part, const float* __restrict__ ml,
    __nv_bfloat16* __restrict__ ctx16)
{
    const int idx = blockIdx.x * 256 + threadIdx.x;
    const int row = idx / (EMB / 4);
    const int c4  = idx % (EMB / 4);
    const int h   = (c4 * 4) >> 6;

    float m[NSPLIT_K], lv[NSPLIT_K];
#pragma unroll
    for (int p = 0; p < NSPLIT_K; p++) {
        float2 v = *(const float2*)(ml + (((size_t)p * HEADS + h) * SEQ + row) * 2);
        m[p] = v.x; lv[p] = v.y;
    }
    const float M = fmaxf(m[0], fmaxf(m[1], m[2]));
    const float w0 = ex2f(m[0] - M), w1 = ex2f(m[1] - M), w2 = ex2f(m[2] - M);
    const float inv = 1.0f / (lv[0] * w0 + lv[1] * w1 + lv[2] * w2);

    const size_t off = (size_t)row * EMB + c4 * 4;
    float4 a = *(const float4*)(part + off);
    float4 b = *(const float4*)(part + (size_t)SEQ * EMB + off);
    float4 c = *(const float4*)(part + 2 * (size_t)SEQ * EMB + off);
    float4 o;
    o.x = (a.x * w0 + b.x * w1 + c.x * w2) * inv;
    o.y = (a.y * w0 + b.y * w1 + c.y * w2) * inv;
    o.z = (a.z * w0 + b.z * w1 + c.z * w2) * inv;
    o.w = (a.w * w0 + b.w * w1 + c.w * w2) * inv;

    uint32_t h0, m0_, l0_, h1, m1_, l1_;
    split_pair_bf(o.x, o.y, h0, m0_, l0_, false);
    split_pair_bf(o.z, o.w, h1, m1_, l1_, false);
    *(uint2*)(ctx16 + off)                       = make_uint2(h0, h1);
    *(uint2*)(ctx16 + (size_t)SEQ * EMB + off)   = make_uint2(m0_, m1_);
}

// ---------------------------------------------------------------------------
extern "C" void kernel_launch(void* const* d_in, const int* in_sizes, int n_in,
                              void* d_out, int out_size)
{
    (void)in_sizes; (void)n_in; (void)out_size;
    const float* x     = (const float*)d_in[0];   // [1,4096,768]
    const float* qkv_w = (const float*)d_in[1];   // [2304,768]
    const float* out_w = (const float*)d_in[2];   // [768,768]
    const float* out_b = (const float*)d_in[3];   // [768]
    float* out = (float*)d_out;                   // [1,4096,768]

    float *qkv = nullptr, *part = nullptr, *ml = nullptr;
    __half *k16 = nullptr, *v16 = nullptr;
    __nv_bfloat16 *x16 = nullptr, *w316 = nullptr, *w216 = nullptr, *ctx16 = nullptr;
    cudaGetSymbolAddress((void**)&qkv, g_qkv);
    cudaGetSymbolAddress((void**)&k16, g_k16);
    cudaGetSymbolAddress((void**)&v16, g_v16);
    cudaGetSymbolAddress((void**)&part, g_part);
    cudaGetSymbolAddress((void**)&ml, g_ml);
    cudaGetSymbolAddress((void**)&x16, g_x16);
    cudaGetSymbolAddress((void**)&w316, g_w316);
    cudaGetSymbolAddress((void**)&w216, g_w216);
    cudaGetSymbolAddress((void**)&ctx16, g_ctx16);

    // 0) Pre-split GEMM operands into bf16 limb planes
    split_bf_kernel<3><<<(SEQ * EMB) / 2048, 256>>>(x, x16, (size_t)SEQ * EMB);
    split_bf_kernel<3><<<(QKV_LD * EMB) / 2048, 256>>>(qkv_w, w316, (size_t)QKV_LD * EMB);
    split_bf_kernel<2><<<(EMB * EMB) / 2048, 256>>>(out_w, w216, (size_t)EMB * EMB);

    // 1) QKV projection (HMMA bf16x3, pre-split operands)
    const int smem3 = 6 * LT * (int)sizeof(__nv_bfloat16);
    cudaFuncSetAttribute(hmma_gemm_pre<3>,
                         cudaFuncAttributeMaxDynamicSharedMemorySize, smem3);
    hmma_gemm_pre<3><<<dim3(QKV_LD / 128, SEQ / 128), 256, smem3>>>(
        x16, (size_t)SEQ * EMB, w316, (size_t)QKV_LD * EMB,
        nullptr, qkv, SEQ, QKV_LD, EMB);

    // 2) K/V fp16 limb pre-split
    prep_k<<<768, 256>>>(qkv, k16);
    prep_v<<<dim3(64, HEADS), 256>>>(qkv, v16);

    // 3) HMMA flash attention, split-K x3, register-resident P
    cudaFuncSetAttribute(attn_hmma,
                         cudaFuncAttributeMaxDynamicSharedMemorySize, ATTN_SMEM_BYTES);
    attn_hmma<<<dim3(SEQ / 128, HEADS, NSPLIT_K), 256, ATTN_SMEM_BYTES>>>(
        qkv, k16, v16, part, ml);

    // 4) Merge partials -> ctx bf16 limbs
    merge_kernel<<<(SEQ * EMB / 4) / 256, 256>>>(part, ml, ctx16);

    // 5) Output projection + bias (HMMA bf16x2, pre-split operands)
    const int smem2 = 4 * LT * (int)sizeof(__nv_bfloat16);
    cudaFuncSetAttribute(hmma_gemm_pre<2>,
                         cudaFuncAttributeMaxDynamicSharedMemorySize, smem2);
    hmma_gemm_pre<2><<<dim3(EMB / 128, SEQ / 128), 256, smem2>>>(
        ctx16, (size_t)SEQ * EMB, w216, (size_t)EMB * EMB,
        out_b, out, SEQ, EMB, EMB);
}

// round 15
// speedup vs baseline: 1.0289x; 1.0289x over previous
#include <cuda_runtime.h>
#include <cuda_bf16.h>
#include <cuda_fp16.h>
#include <math.h>
#include <stdint.h>

#define EMB 768
#define HEADS 12
#define HD 64
#define SEQ 4096
#define QKV_LD (3 * EMB)   // 2304
#define LIMB ((size_t)HEADS * SEQ * HD)   // halves per K/V limb plane
#define LOG2E 1.4426950408889634f
#define NSPLIT_K 3

// Scratch (static device globals — no allocation)
__device__ __align__(16) float g_qkv[(size_t)SEQ * QKV_LD];        // Q|K|V fp32
__device__ __align__(16) __half g_k16[2 * HEADS * SEQ * HD];       // [limb][h][k][d]
__device__ __align__(16) __half g_v16[2 * HEADS * SEQ * HD];       // [limb][h][c][k]
__device__ __align__(16) float g_part[(size_t)NSPLIT_K * SEQ * EMB];
__device__ __align__(16) float g_ml[(size_t)NSPLIT_K * HEADS * SEQ * 2];
__device__ __align__(16) __nv_bfloat16 g_w216[2 * (size_t)EMB * EMB];
__device__ __align__(16) __nv_bfloat16 g_ctx16[2 * (size_t)SEQ * EMB];

// ---------------------------------------------------------------------------
// HMMA helpers (mma.sync — supported on base sm_103 target)
// ---------------------------------------------------------------------------
__device__ __forceinline__ void mma_bf16(float* d, const uint32_t* a, const uint32_t* b) {
    asm volatile(
        "mma.sync.aligned.m16n8k16.row.col.f32.bf16.bf16.f32 "
        "{%0,%1,%2,%3}, {%4,%5,%6,%7}, {%8,%9}, {%0,%1,%2,%3};"
        : "+f"(d[0]), "+f"(d[1]), "+f"(d[2]), "+f"(d[3])
        : "r"(a[0]), "r"(a[1]), "r"(a[2]), "r"(a[3]), "r"(b[0]), "r"(b[1]));
}
__device__ __forceinline__ void mma_f16(float* d, const uint32_t* a, const uint32_t* b) {
    asm volatile(
        "mma.sync.aligned.m16n8k16.row.col.f32.f16.f16.f32 "
        "{%0,%1,%2,%3}, {%4,%5,%6,%7}, {%8,%9}, {%0,%1,%2,%3};"
        : "+f"(d[0]), "+f"(d[1]), "+f"(d[2]), "+f"(d[3])
        : "r"(a[0]), "r"(a[1]), "r"(a[2]), "r"(a[3]), "r"(b[0]), "r"(b[1]));
}
__device__ __forceinline__ uint32_t h2bits(__half2 h) { return *(uint32_t*)&h; }
__device__ __forceinline__ float ex2f(float x) {
    float r; asm("ex2.approx.ftz.f32 %0, %1;" : "=f"(r) : "f"(x)); return r;
}

// fp32 pair -> fp16 hi/lo limbs (packed f16x2: x -> low half)
__device__ __forceinline__ void split_h2(float x, float y, uint32_t& hi, uint32_t& lo) {
    __half2 h = __floats2half2_rn(x, y);
    float2 f = __half22float2(h);
    __half2 l = __floats2half2_rn(x - f.x, y - f.y);
    hi = h2bits(h);
    lo = h2bits(l);
}

// fp32 pair -> bf16 limb split
__device__ __forceinline__ void split_pair_bf(
    float x, float y, uint32_t& h, uint32_t& m, uint32_t& l, bool want3)
{
    __nv_bfloat162 hb = __float22bfloat162_rn(make_float2(x, y));
    float2 hf = __bfloat1622float2(hb);
    float rx = x - hf.x, ry = y - hf.y;
    __nv_bfloat162 mb = __float22bfloat162_rn(make_float2(rx, ry));
    h = *(uint32_t*)&hb;
    m = *(uint32_t*)&mb;
    if (want3) {
        float2 mf = __bfloat1622float2(mb);
        __nv_bfloat162 lb = __float22bfloat162_rn(make_float2(rx - mf.x, ry - mf.y));
        l = *(uint32_t*)&lb;
    } else {
        l = 0;
    }
}

#define LT (128 * 40)   // bf16 elements per limb tile

// ---------------------------------------------------------------------------
// HMMA GEMM with IN-KERNEL bf16 limb split (round-8 proven, 234us for QKV).
// C[M,N] = A[M,K] @ B[N,K]^T (+bias). 128x128 tile, BK=32, 2 CTAs/SM.
// ---------------------------------------------------------------------------
template<int NSPLIT>
__global__ __launch_bounds__(256, 2) void hmma_gemm_abt(
    const float* __restrict__ A, const float* __restrict__ B,
    const float* __restrict__ bias, float* __restrict__ C,
    int M, int N, int K)
{
    extern __shared__ __align__(16) char smem[];
    __nv_bfloat16* As = (__nv_bfloat16*)smem;
    __nv_bfloat16* Bs = As + NSPLIT * LT;

    const int tid  = threadIdx.x;
    const int lane = tid & 31;
    const int wid  = tid >> 5;
    const int wm   = wid >> 2;
    const int wn   = wid & 3;
    const int grp  = lane >> 2;
    const int tg   = lane & 3;
    const int bm0  = blockIdx.y * 128;
    const int bn0  = blockIdx.x * 128;

    float d[4][4][4];
#pragma unroll
    for (int am = 0; am < 4; am++)
#pragma unroll
        for (int an = 0; an < 4; an++)
#pragma unroll
            for (int r = 0; r < 4; r++) d[am][an][r] = 0.0f;

    const int NPR = (NSPLIT == 3) ? 6 : 3;
    const int PA[6] = {0, 0, 1, 0, 2, 1};
    const int PB[6] = {0, 1, 0, 2, 0, 1};

    for (int k0 = 0; k0 < K; k0 += 32) {
        __syncthreads();
#pragma unroll
        for (int half = 0; half < 2; half++) {
            const float* src = half ? (B + (size_t)bn0 * K) : (A + (size_t)bm0 * K);
            __nv_bfloat16* dst = half ? Bs : As;
#pragma unroll
            for (int it = 0; it < 2; it++) {
                const int f   = tid + it * 256;
                const int row = f >> 2;
                const int c8  = f & 3;
                const float* p = src + (size_t)row * K + k0 + c8 * 8;
                float4 v0 = *(const float4*)p;
                float4 v1 = *(const float4*)(p + 4);
                uint32_t h[4], m[4], l[4];
                split_pair_bf(v0.x, v0.y, h[0], m[0], l[0], NSPLIT == 3);
                split_pair_bf(v0.z, v0.w, h[1], m[1], l[1], NSPLIT == 3);
                split_pair_bf(v1.x, v1.y, h[2], m[2], l[2], NSPLIT == 3);
                split_pair_bf(v1.z, v1.w, h[3], m[3], l[3], NSPLIT == 3);
                const int base = row * 40 + c8 * 8;
#pragma unroll
                for (int j = 0; j < 4; j++) {
                    *(uint32_t*)&dst[0 * LT + base + j * 2] = h[j];
                    *(uint32_t*)&dst[1 * LT + base + j * 2] = m[j];
                    if (NSPLIT == 3)
                        *(uint32_t*)&dst[2 * LT + base + j * 2] = l[j];
                }
            }
        }
        __syncthreads();

#pragma unroll
        for (int ks = 0; ks < 2; ks++) {
#pragma unroll
            for (int p = 0; p < NPR; p++) {
                const int la = PA[p], lb = PB[p];
                uint32_t afr[4][4];
#pragma unroll
                for (int am = 0; am < 4; am++) {
                    const __nv_bfloat16* ap =
                        As + la * LT + (wm * 64 + am * 16 + grp) * 40 + ks * 16 + tg * 2;
                    afr[am][0] = *(const uint32_t*)ap;
                    afr[am][1] = *(const uint32_t*)(ap + 8 * 40);
                    afr[am][2] = *(const uint32_t*)(ap + 8);
                    afr[am][3] = *(const uint32_t*)(ap + 8 * 40 + 8);
                }
#pragma unroll
                for (int an = 0; an < 4; an++) {
                    const __nv_bfloat16* bp =
                        Bs + lb * LT + (wn * 32 + an * 8 + grp) * 40 + ks * 16 + tg * 2;
                    uint32_t bfr[2];
                    bfr[0] = *(const uint32_t*)bp;
                    bfr[1] = *(const uint32_t*)(bp + 8);
#pragma unroll
                    for (int am = 0; am < 4; am++)
                        mma_bf16(d[am][an], afr[am], bfr);
                }
            }
        }
    }

#pragma unroll
    for (int am = 0; am < 4; am++) {
        const int r0 = bm0 + wm * 64 + am * 16 + grp;
#pragma unroll
        for (int an = 0; an < 4; an++) {
            const int c0 = bn0 + wn * 32 + an * 8 + tg * 2;
            float bv0 = 0.0f, bv1 = 0.0f;
            if (bias) { bv0 = bias[c0]; bv1 = bias[c0 + 1]; }
            *(float2*)&C[(size_t)r0 * N + c0] =
                make_float2(d[am][an][0] + bv0, d[am][an][1] + bv1);
            *(float2*)&C[(size_t)(r0 + 8) * N + c0] =
                make_float2(d[am][an][2] + bv0, d[am][an][3] + bv1);
        }
    }
}

// ---------------------------------------------------------------------------
// HMMA GEMM on PRE-SPLIT bf16 limbs (for out-proj: A=ctx16, B=w216).
// ---------------------------------------------------------------------------
template<int NSPLIT>
__global__ __launch_bounds__(256, 2) void hmma_gemm_pre(
    const __nv_bfloat16* __restrict__ A, size_t sA,
    const __nv_bfloat16* __restrict__ B, size_t sB,
    const float* __restrict__ bias, float* __restrict__ C,
    int M, int N, int K)
{
    extern __shared__ __align__(16) char smem[];
    __nv_bfloat16* As = (__nv_bfloat16*)smem;
    __nv_bfloat16* Bs = As + NSPLIT * LT;

    const int tid  = threadIdx.x;
    const int lane = tid & 31;
    const int wid  = tid >> 5;
    const int wm   = wid >> 2;
    const int wn   = wid & 3;
    const int grp  = lane >> 2;
    const int tg   = lane & 3;
    const int bm0  = blockIdx.y * 128;
    const int bn0  = blockIdx.x * 128;

    float d[4][4][4];
#pragma unroll
    for (int am = 0; am < 4; am++)
#pragma unroll
        for (int an = 0; an < 4; an++)
#pragma unroll
            for (int r = 0; r < 4; r++) d[am][an][r] = 0.0f;

    const int NPR = (NSPLIT == 3) ? 6 : 3;
    const int PA[6] = {0, 0, 1, 0, 2, 1};
    const int PB[6] = {0, 1, 0, 2, 0, 1};

    for (int k0 = 0; k0 < K; k0 += 32) {
        __syncthreads();
#pragma unroll
        for (int half = 0; half < 2; half++) {
            const __nv_bfloat16* src = half ? (B + (size_t)bn0 * K) : (A + (size_t)bm0 * K);
            const size_t ps = half ? sB : sA;
            __nv_bfloat16* dst = half ? Bs : As;
#pragma unroll
            for (int it = 0; it < 2; it++) {
                const int f   = tid + it * 256;
                const int row = f >> 2;
                const int c8  = f & 3;
                const size_t go = (size_t)row * K + k0 + c8 * 8;
                const int   so = row * 40 + c8 * 8;
#pragma unroll
                for (int lb = 0; lb < NSPLIT; lb++) {
                    uint4 v = *(const uint4*)(src + lb * ps + go);
                    *(uint4*)&dst[lb * LT + so] = v;
                }
            }
        }
        __syncthreads();

#pragma unroll
        for (int ks = 0; ks < 2; ks++) {
#pragma unroll
            for (int p = 0; p < NPR; p++) {
                const int la = PA[p], lb = PB[p];
                uint32_t afr[4][4];
#pragma unroll
                for (int am = 0; am < 4; am++) {
                    const __nv_bfloat16* ap =
                        As + la * LT + (wm * 64 + am * 16 + grp) * 40 + ks * 16 + tg * 2;
                    afr[am][0] = *(const uint32_t*)ap;
                    afr[am][1] = *(const uint32_t*)(ap + 8 * 40);
                    afr[am][2] = *(const uint32_t*)(ap + 8);
                    afr[am][3] = *(const uint32_t*)(ap + 8 * 40 + 8);
                }
#pragma unroll
                for (int an = 0; an < 4; an++) {
                    const __nv_bfloat16* bp =
                        Bs + lb * LT + (wn * 32 + an * 8 + grp) * 40 + ks * 16 + tg * 2;
                    uint32_t bfr[2];
                    bfr[0] = *(const uint32_t*)bp;
                    bfr[1] = *(const uint32_t*)(bp + 8);
#pragma unroll
                    for (int am = 0; am < 4; am++)
                        mma_bf16(d[am][an], afr[am], bfr);
                }
            }
        }
    }

#pragma unroll
    for (int am = 0; am < 4; am++) {
        const int r0 = bm0 + wm * 64 + am * 16 + grp;
#pragma unroll
        for (int an = 0; an < 4; an++) {
            const int c0 = bn0 + wn * 32 + an * 8 + tg * 2;
            float bv0 = 0.0f, bv1 = 0.0f;
            if (bias) { bv0 = bias[c0]; bv1 = bias[c0 + 1]; }
            *(float2*)&C[(size_t)r0 * N + c0] =
                make_float2(d[am][an][0] + bv0, d[am][an][1] + bv1);
            *(float2*)&C[(size_t)(r0 + 8) * N + c0] =
                make_float2(d[am][an][2] + bv0, d[am][an][3] + bv1);
        }
    }
}

// ---------------------------------------------------------------------------
// Prep: fp32 -> NS bf16 limb planes (for out_w only; tiny).
// ---------------------------------------------------------------------------
template<int NS>
__global__ __launch_bounds__(256) void split_bf_kernel(
    const float* __restrict__ src, __nv_bfloat16* __restrict__ dst, size_t n)
{
    const size_t i = ((size_t)blockIdx.x * 256 + threadIdx.x) * 8;
    float4 v0 = *(const float4*)(src + i);
    float4 v1 = *(const float4*)(src + i + 4);
    uint32_t h[4], m[4], l[4];
    split_pair_bf(v0.x, v0.y, h[0], m[0], l[0], NS == 3);
    split_pair_bf(v0.z, v0.w, h[1], m[1], l[1], NS == 3);
    split_pair_bf(v1.x, v1.y, h[2], m[2], l[2], NS == 3);
    split_pair_bf(v1.z, v1.w, h[3], m[3], l[3], NS == 3);
    *(uint4*)(dst + i)     = make_uint4(h[0], h[1], h[2], h[3]);
    *(uint4*)(dst + n + i) = make_uint4(m[0], m[1], m[2], m[3]);
    if (NS == 3)
        *(uint4*)(dst + 2 * n + i) = make_uint4(l[0], l[1], l[2], l[3]);
}

// ---------------------------------------------------------------------------
// Prep K: fp32 -> fp16 hi/lo limbs, layout [limb][h][k][d]. (proven)
// ---------------------------------------------------------------------------
__global__ __launch_bounds__(256) void prep_k(
    const float* __restrict__ qkv, __half* __restrict__ k16)
{
    const int u  = blockIdx.x * 256 + threadIdx.x;
    const int hk = u >> 2, ch = u & 3;
    const int h = hk >> 12, k = hk & 4095;
    const float* src = qkv + (size_t)k * QKV_LD + EMB + h * HD + ch * 16;
    __half* dh = k16 + ((size_t)h * SEQ + k) * HD + ch * 16;

    uint32_t hi[8], lo[8];
#pragma unroll
    for (int j = 0; j < 4; j++) {
        float4 v = *(const float4*)(src + j * 4);
        split_h2(v.x, v.y, hi[j * 2], lo[j * 2]);
        split_h2(v.z, v.w, hi[j * 2 + 1], lo[j * 2 + 1]);
    }
    *(uint4*)dh       = make_uint4(hi[0], hi[1], hi[2], hi[3]);
    *(uint4*)(dh + 8) = make_uint4(hi[4], hi[5], hi[6], hi[7]);
    __half* dl = dh + LIMB;
    *(uint4*)dl       = make_uint4(lo[0], lo[1], lo[2], lo[3]);
    *(uint4*)(dl + 8) = make_uint4(lo[4], lo[5], lo[6], lo[7]);
}

// ---------------------------------------------------------------------------
// Prep V: split + transpose to [limb][h][c][k]. (proven)
// ---------------------------------------------------------------------------
__global__ __launch_bounds__(256) void prep_v(
    const float* __restrict__ qkv, __half* __restrict__ v16)
{
    __shared__ __align__(16) __half sv[2][64][80];
    const int h  = blockIdx.y, kb = blockIdx.x;
    const int t  = threadIdx.x;
    {
        const int k = t >> 2, ch = t & 3;
        const float* src = qkv + (size_t)(kb * 64 + k) * QKV_LD + 2 * EMB + h * HD + ch * 16;
#pragma unroll
        for (int j = 0; j < 16; j += 2) {
            float2 v = *(const float2*)(src + j);
            __half2 a = __floats2half2_rn(v.x, v.y);
            float2 f = __half22float2(a);
            __half2 r = __floats2half2_rn(v.x - f.x, v.y - f.y);
            const int c = ch * 16 + j;
            sv[0][c][k]     = __low2half(a);
            sv[0][c + 1][k] = __high2half(a);
            sv[1][c][k]     = __low2half(r);
            sv[1][c + 1][k] = __high2half(r);
        }
    }
    __syncthreads();
    {
        const int c = t >> 2, kc = t & 3;
        __half* dst = v16 + ((size_t)h * HD + c) * SEQ + kb * 64 + kc * 16;
#pragma unroll
        for (int j = 0; j < 2; j++) {
            *(uint4*)(dst + j * 8)        = *(const uint4*)&sv[0][c][kc * 16 + j * 8];
            *(uint4*)(dst + LIMB + j * 8) = *(const uint4*)&sv[1][c][kc * 16 + j * 8];
        }
    }
}

// ---------------------------------------------------------------------------
// HMMA flash attention, split-K x3, register-resident P (round-14, kept).
// ---------------------------------------------------------------------------
#define SQH 0                    // Q hi  [128][72]
#define SQL (SQH + 128 * 72)     // Q lo
#define SKH (SQL + 128 * 72)     // K hi  [64 key][72 d]
#define SKL (SKH + 64 * 72)      // K lo
#define SVH (SKL + 64 * 72)      // V^T hi [64 c][72 k]
#define SVL (SVH + 64 * 72)      // V^T lo
#define ATTN_HALVES (SVL + 64 * 72)           // 36864
#define ATTN_SMEM_BYTES (ATTN_HALVES * 2)     // 73728

__global__ __launch_bounds__(256, 2) void attn_hmma(
    const float* __restrict__ qkv,
    const __half* __restrict__ k16, const __half* __restrict__ v16,
    float* __restrict__ opart, float* __restrict__ ml)
{
    extern __shared__ __align__(16) __half sh[];
    const int tid  = threadIdx.x;
    const int lane = tid & 31;
    const int wid  = tid >> 5;
    const int grp  = lane >> 2;
    const int tg   = lane & 3;
    const int h    = blockIdx.y;
    const int q0   = blockIdx.x * 128;
    const int sp   = blockIdx.z;

    const int kt0 = (sp == 0) ? 0 : (sp == 1 ? 22 : 43);
    const int kt1 = (sp == 0) ? 22 : (sp == 1 ? 43 : 64);

    // ---- Load Q tile, scale by 8*log2e, split into fp16 limbs ----
#pragma unroll
    for (int f = tid; f < 512; f += 256) {
        const int row = f >> 2, ch = f & 3;
        const float* p = qkv + (size_t)(q0 + row) * QKV_LD + h * HD + ch * 16;
        uint32_t hi[8], lo[8];
#pragma unroll
        for (int j = 0; j < 4; j++) {
            float4 v = *(const float4*)(p + j * 4);
            const float sc = 8.0f * LOG2E;
            split_h2(v.x * sc, v.y * sc, hi[j * 2], lo[j * 2]);
            split_h2(v.z * sc, v.w * sc, hi[j * 2 + 1], lo[j * 2 + 1]);
        }
        const int o = row * 72 + ch * 16;
        *(uint4*)&sh[SQH + o]     = make_uint4(hi[0], hi[1], hi[2], hi[3]);
        *(uint4*)&sh[SQH + o + 8] = make_uint4(hi[4], hi[5], hi[6], hi[7]);
        *(uint4*)&sh[SQL + o]     = make_uint4(lo[0], lo[1], lo[2], lo[3]);
        *(uint4*)&sh[SQL + o + 8] = make_uint4(lo[4], lo[5], lo[6], lo[7]);
    }

    const __half* kP = k16 + (size_t)h * SEQ * HD;
    const __half* vP = v16 + (size_t)h * HD * SEQ;

    int clt[4], crow[4], cseg[4];
#pragma unroll
    for (int i = 0; i < 4; i++) {
        const int g = tid + i * 256;
        clt[i]  = g >> 9;
        crow[i] = (g >> 3) & 63;
        cseg[i] = g & 7;
    }

    auto sts_chunk = [&](int base_h, int base_l, int i, uint4 v) {
        const int off = (base_h + (clt[i] ? (base_l - base_h) : 0))
                        + crow[i] * 72 + cseg[i] * 8;
        *(uint2*)&sh[off]     = make_uint2(v.x, v.y);
        *(uint2*)&sh[off + 4] = make_uint2(v.z, v.w);
    };

    // ---- Preload K(kt0) and V(kt0) ----
    {
        uint4 kc4[4], vc4[4];
#pragma unroll
        for (int i = 0; i < 4; i++) {
            kc4[i] = *(const uint4*)(kP + clt[i] * LIMB
                         + (size_t)(kt0 * 64 + crow[i]) * HD + cseg[i] * 8);
            vc4[i] = *(const uint4*)(vP + clt[i] * LIMB
                         + (size_t)crow[i] * SEQ + kt0 * 64 + cseg[i] * 8);
        }
#pragma unroll
        for (int i = 0; i < 4; i++) {
            sts_chunk(SKH, SKL, i, kc4[i]);
            sts_chunk(SVH, SVL, i, vc4[i]);
        }
    }
    __syncthreads();

    float m0 = -1e30f, m1 = -1e30f, l0 = 0.0f, l1 = 0.0f;
    float O[8][4];
#pragma unroll
    for (int nt = 0; nt < 8; nt++)
#pragma unroll
        for (int r = 0; r < 4; r++) O[nt][r] = 0.0f;

    const int qrow = (wid * 16 + grp) * 72 + tg * 2;

    for (int it = kt0; it < kt1; it++) {
        const int kt = it * 64;
        const bool pf = (it + 1) < kt1;

        uint4 kc4[4], vc4[4];
        if (pf) {
#pragma unroll
            for (int i = 0; i < 4; i++) {
                kc4[i] = *(const uint4*)(kP + clt[i] * LIMB
                             + (size_t)(kt + 64 + crow[i]) * HD + cseg[i] * 8);
                vc4[i] = *(const uint4*)(vP + clt[i] * LIMB
                             + (size_t)crow[i] * SEQ + kt + 64 + cseg[i] * 8);
            }
        }

        // ---- S = Q K^T (3 fp16 limb products) ----
        float s[8][4];
#pragma unroll
        for (int nt = 0; nt < 8; nt++)
#pragma unroll
            for (int r = 0; r < 4; r++) s[nt][r] = 0.0f;

#pragma unroll
        for (int ks = 0; ks < 4; ks++) {
            const int qa = qrow + ks * 16;
            uint32_t ah[4], al_[4];
            ah[0] = *(const uint32_t*)&sh[SQH + qa];
            ah[1] = *(const uint32_t*)&sh[SQH + qa + 8 * 72];
            ah[2] = *(const uint32_t*)&sh[SQH + qa + 8];
            ah[3] = *(const uint32_t*)&sh[SQH + qa + 8 * 72 + 8];
            al_[0] = *(const uint32_t*)&sh[SQL + qa];
            al_[1] = *(const uint32_t*)&sh[SQL + qa + 8 * 72];
            al_[2] = *(const uint32_t*)&sh[SQL + qa + 8];
            al_[3] = *(const uint32_t*)&sh[SQL + qa + 8 * 72 + 8];
#pragma unroll
            for (int nt = 0; nt < 8; nt++) {
                const int ka = (nt * 8 + grp) * 72 + ks * 16 + tg * 2;
                uint32_t kh[2], kl[2];
                kh[0] = *(const uint32_t*)&sh[SKH + ka];
                kh[1] = *(const uint32_t*)&sh[SKH + ka + 8];
                kl[0] = *(const uint32_t*)&sh[SKL + ka];
                kl[1] = *(const uint32_t*)&sh[SKL + ka + 8];
                mma_f16(s[nt], ah, kh);
                mma_f16(s[nt], al_, kh);
                mma_f16(s[nt], ah, kl);
            }
        }

        // ---- Online softmax (log2 domain) ----
        float mx0 = -1e30f, mx1 = -1e30f;
#pragma unroll
        for (int nt = 0; nt < 8; nt++) {
            mx0 = fmaxf(mx0, fmaxf(s[nt][0], s[nt][1]));
            mx1 = fmaxf(mx1, fmaxf(s[nt][2], s[nt][3]));
        }
        mx0 = fmaxf(mx0, __shfl_xor_sync(0xffffffffu, mx0, 1));
        mx0 = fmaxf(mx0, __shfl_xor_sync(0xffffffffu, mx0, 2));
        mx1 = fmaxf(mx1, __shfl_xor_sync(0xffffffffu, mx1, 1));
        mx1 = fmaxf(mx1, __shfl_xor_sync(0xffffffffu, mx1, 2));

        const float mn0 = fmaxf(m0, mx0), mn1 = fmaxf(m1, mx1);
        const float al0 = ex2f(m0 - mn0), al1 = ex2f(m1 - mn1);
        m0 = mn0; m1 = mn1;

        float sum0 = 0.0f, sum1 = 0.0f;
#pragma unroll
        for (int nt = 0; nt < 8; nt++) {
            s[nt][0] = ex2f(s[nt][0] - mn0); sum0 += s[nt][0];
            s[nt][1] = ex2f(s[nt][1] - mn0); sum0 += s[nt][1];
            s[nt][2] = ex2f(s[nt][2] - mn1); sum1 += s[nt][2];
            s[nt][3] = ex2f(s[nt][3] - mn1); sum1 += s[nt][3];
        }
        sum0 += __shfl_xor_sync(0xffffffffu, sum0, 1);
        sum0 += __shfl_xor_sync(0xffffffffu, sum0, 2);
        sum1 += __shfl_xor_sync(0xffffffffu, sum1, 1);
        sum1 += __shfl_xor_sync(0xffffffffu, sum1, 2);
        l0 = l0 * al0 + sum0;
        l1 = l1 * al1 + sum1;

#pragma unroll
        for (int nt = 0; nt < 8; nt++) {
            O[nt][0] *= al0; O[nt][1] *= al0;
            O[nt][2] *= al1; O[nt][3] *= al1;
        }

        // ---- O += P V: P packed from S fragments IN REGISTERS ----
#pragma unroll
        for (int kc = 0; kc < 4; kc++) {
            uint32_t ph[4], pl[4];
            split_h2(s[2 * kc][0],     s[2 * kc][1],     ph[0], pl[0]);
            split_h2(s[2 * kc][2],     s[2 * kc][3],     ph[1], pl[1]);
            split_h2(s[2 * kc + 1][0], s[2 * kc + 1][1], ph[2], pl[2]);
            split_h2(s[2 * kc + 1][2], s[2 * kc + 1][3], ph[3], pl[3]);
#pragma unroll
            for (int nt = 0; nt < 8; nt++) {
                const int va = (nt * 8 + grp) * 72 + kc * 16 + tg * 2;
                uint32_t vh[2], vl[2];
                vh[0] = *(const uint32_t*)&sh[SVH + va];
                vh[1] = *(const uint32_t*)&sh[SVH + va + 8];
                vl[0] = *(const uint32_t*)&sh[SVL + va];
                vl[1] = *(const uint32_t*)&sh[SVL + va + 8];
                mma_f16(O[nt], ph, vh);
                mma_f16(O[nt], pl, vh);
                mma_f16(O[nt], ph, vl);
            }
        }

        if (pf) {
            __syncthreads();
#pragma unroll
            for (int i = 0; i < 4; i++) {
                sts_chunk(SKH, SKL, i, kc4[i]);
                sts_chunk(SVH, SVL, i, vc4[i]);
            }
            __syncthreads();
        }
    }

    // ---- Write UNNORMALIZED partial O + (m,l) per row ----
    const int r0 = q0 + wid * 16 + grp;
    float* op = opart + (size_t)sp * SEQ * EMB;
#pragma unroll
    for (int nt = 0; nt < 8; nt++) {
        const int c = h * HD + nt * 8 + tg * 2;
        *(float2*)&op[(size_t)r0 * EMB + c]       = make_float2(O[nt][0], O[nt][1]);
        *(float2*)&op[(size_t)(r0 + 8) * EMB + c] = make_float2(O[nt][2], O[nt][3]);
    }
    if (tg == 0) {
        float* mlp = ml + (((size_t)sp * HEADS + h) * SEQ) * 2;
        *(float2*)&mlp[(size_t)r0 * 2]       = make_float2(m0, l0);
        *(float2*)&mlp[(size_t)(r0 + 8) * 2] = make_float2(m1, l1);
    }
}

// ---------------------------------------------------------------------------
// Merge the 3 split-K partials; emit ctx as 2 bf16 limb planes.
// ---------------------------------------------------------------------------
__global__ __launch_bounds__(256) void merge_kernel(
    const float* __restrict__ part, const float* __restrict__ ml,
    __nv_bfloat16* __restrict__ ctx16)
{
    const int idx = blockIdx.x * 256 + threadIdx.x;
    const int row = idx / (EMB / 4);
    const int c4  = idx % (EMB / 4);
    const int h   = (c4 * 4) >> 6;

    float m[NSPLIT_K], lv[NSPLIT_K];
#pragma unroll
    for (int p = 0; p < NSPLIT_K; p++) {
        float2 v = *(const float2*)(ml + (((size_t)p * HEADS + h) * SEQ + row) * 2);
        m[p] = v.x; lv[p] = v.y;
    }
    const float M = fmaxf(m[0], fmaxf(m[1], m[2]));
    const float w0 = ex2f(m[0] - M), w1 = ex2f(m[1] - M), w2 = ex2f(m[2] - M);
    const float inv = 1.0f / (lv[0] * w0 + lv[1] * w1 + lv[2] * w2);

    const size_t off = (size_t)row * EMB + c4 * 4;
    float4 a = *(const float4*)(part + off);
    float4 b = *(const float4*)(part + (size_t)SEQ * EMB + off);
    float4 c = *(const float4*)(part + 2 * (size_t)SEQ * EMB + off);
    float4 o;
    o.x = (a.x * w0 + b.x * w1 + c.x * w2) * inv;
    o.y = (a.y * w0 + b.y * w1 + c.y * w2) * inv;
    o.z = (a.z * w0 + b.z * w1 + c.z * w2) * inv;
    o.w = (a.w * w0 + b.w * w1 + c.w * w2) * inv;

    uint32_t h0, m0_, l0_, h1, m1_, l1_;
    split_pair_bf(o.x, o.y, h0, m0_, l0_, false);
    split_pair_bf(o.z, o.w, h1, m1_, l1_, false);
    *(uint2*)(ctx16 + off)                     = make_uint2(h0, h1);
    *(uint2*)(ctx16 + (size_t)SEQ * EMB + off) = make_uint2(m0_, m1_);
}

// ---------------------------------------------------------------------------
extern "C" void kernel_launch(void* const* d_in, const int* in_sizes, int n_in,
                              void* d_out, int out_size)
{
    (void)in_sizes; (void)n_in; (void)out_size;
    const float* x     = (const float*)d_in[0];   // [1,4096,768]
    const float* qkv_w = (const float*)d_in[1];   // [2304,768]
    const float* out_w = (const float*)d_in[2];   // [768,768]
    const float* out_b = (const float*)d_in[3];   // [768]
    float* out = (float*)d_out;                   // [1,4096,768]

    float *qkv = nullptr, *part = nullptr, *ml = nullptr;
    __half *k16 = nullptr, *v16 = nullptr;
    __nv_bfloat16 *w216 = nullptr, *ctx16 = nullptr;
    cudaGetSymbolAddress((void**)&qkv, g_qkv);
    cudaGetSymbolAddress((void**)&k16, g_k16);
    cudaGetSymbolAddress((void**)&v16, g_v16);
    cudaGetSymbolAddress((void**)&part, g_part);
    cudaGetSymbolAddress((void**)&ml, g_ml);
    cudaGetSymbolAddress((void**)&w216, g_w216);
    cudaGetSymbolAddress((void**)&ctx16, g_ctx16);

    // 0) Pre-split out_w only (tiny, ~2us)
    split_bf_kernel<2><<<(EMB * EMB) / 2048, 256>>>(out_w, w216, (size_t)EMB * EMB);

    // 1) QKV projection (HMMA bf16x3, in-kernel split — proven 234us)
    const int smem3 = 6 * LT * (int)sizeof(__nv_bfloat16);
    cudaFuncSetAttribute(hmma_gemm_abt<3>,
                         cudaFuncAttributeMaxDynamicSharedMemorySize, smem3);
    hmma_gemm_abt<3><<<dim3(QKV_LD / 128, SEQ / 128), 256, smem3>>>(
        x, qkv_w, nullptr, qkv, SEQ, QKV_LD, EMB);

    // 2) K/V fp16 limb pre-split
    prep_k<<<768, 256>>>(qkv, k16);
    prep_v<<<dim3(64, HEADS), 256>>>(qkv, v16);

    // 3) HMMA flash attention, split-K x3, register-resident P
    cudaFuncSetAttribute(attn_hmma,
                         cudaFuncAttributeMaxDynamicSharedMemorySize, ATTN_SMEM_BYTES);
    attn_hmma<<<dim3(SEQ / 128, HEADS, NSPLIT_K), 256, ATTN_SMEM_BYTES>>>(
        qkv, k16, v16, part, ml);

    // 4) Merge partials -> ctx bf16 limbs
    merge_kernel<<<(SEQ * EMB / 4) / 256, 256>>>(part, ml, ctx16);

    // 5) Output projection + bias (HMMA bf16x2, pre-split operands)
    const int smem2 = 4 * LT * (int)sizeof(__nv_bfloat16);
    cudaFuncSetAttribute(hmma_gemm_pre<2>,
                         cudaFuncAttributeMaxDynamicSharedMemorySize, smem2);
    hmma_gemm_pre<2><<<dim3(EMB / 128, SEQ / 128), 256, smem2>>>(
        ctx16, (size_t)SEQ * EMB, w216, (size_t)EMB * EMB,
        out_b, out, SEQ, EMB, EMB);
}

// round 16
// speedup vs baseline: 1.0438x; 1.0145x over previous
#include <cuda_runtime.h>
#include <cuda_bf16.h>
#include <cuda_fp16.h>
#include <math.h>
#include <stdint.h>

#define EMB 768
#define HEADS 12
#define HD 64
#define SEQ 4096
#define QKV_LD (3 * EMB)   // 2304
#define LIMB ((size_t)HEADS * SEQ * HD)   // halves per K/V limb plane
#define LOG2E 1.4426950408889634f
#define NSPLIT_K 3

// Scratch (static device globals — no allocation)
__device__ __align__(16) float g_qkv[(size_t)SEQ * QKV_LD];        // Q|K|V fp32
__device__ __align__(16) __half g_k16[2 * HEADS * SEQ * HD];       // [limb][h][k][d]
__device__ __align__(16) __half g_v16[2 * HEADS * SEQ * HD];       // [limb][h][c][k]
__device__ __align__(16) float g_part[(size_t)NSPLIT_K * SEQ * EMB];
__device__ __align__(16) float g_ml[(size_t)NSPLIT_K * HEADS * SEQ * 2];
__device__ __align__(16) __nv_bfloat16 g_w216[2 * (size_t)EMB * EMB];
__device__ __align__(16) __nv_bfloat16 g_ctx16[2 * (size_t)SEQ * EMB];

// ---------------------------------------------------------------------------
// HMMA helpers (mma.sync — supported on base sm_103 target)
// ---------------------------------------------------------------------------
__device__ __forceinline__ void mma_bf16(float* d, const uint32_t* a, const uint32_t* b) {
    asm volatile(
        "mma.sync.aligned.m16n8k16.row.col.f32.bf16.bf16.f32 "
        "{%0,%1,%2,%3}, {%4,%5,%6,%7}, {%8,%9}, {%0,%1,%2,%3};"
        : "+f"(d[0]), "+f"(d[1]), "+f"(d[2]), "+f"(d[3])
        : "r"(a[0]), "r"(a[1]), "r"(a[2]), "r"(a[3]), "r"(b[0]), "r"(b[1]));
}
__device__ __forceinline__ void mma_f16(float* d, const uint32_t* a, const uint32_t* b) {
    asm volatile(
        "mma.sync.aligned.m16n8k16.row.col.f32.f16.f16.f32 "
        "{%0,%1,%2,%3}, {%4,%5,%6,%7}, {%8,%9}, {%0,%1,%2,%3};"
        : "+f"(d[0]), "+f"(d[1]), "+f"(d[2]), "+f"(d[3])
        : "r"(a[0]), "r"(a[1]), "r"(a[2]), "r"(a[3]), "r"(b[0]), "r"(b[1]));
}
__device__ __forceinline__ uint32_t h2bits(__half2 h) { return *(uint32_t*)&h; }
__device__ __forceinline__ float ex2f(float x) {
    float r; asm("ex2.approx.ftz.f32 %0, %1;" : "=f"(r) : "f"(x)); return r;
}

// fp32 pair -> fp16 hi/lo limbs (packed f16x2: x -> low half)
__device__ __forceinline__ void split_h2(float x, float y, uint32_t& hi, uint32_t& lo) {
    __half2 h = __floats2half2_rn(x, y);
    float2 f = __half22float2(h);
    __half2 l = __floats2half2_rn(x - f.x, y - f.y);
    hi = h2bits(h);
    lo = h2bits(l);
}

// fp32 pair -> bf16 limb split
__device__ __forceinline__ void split_pair_bf(
    float x, float y, uint32_t& h, uint32_t& m, uint32_t& l, bool want3)
{
    __nv_bfloat162 hb = __float22bfloat162_rn(make_float2(x, y));
    float2 hf = __bfloat1622float2(hb);
    float rx = x - hf.x, ry = y - hf.y;
    __nv_bfloat162 mb = __float22bfloat162_rn(make_float2(rx, ry));
    h = *(uint32_t*)&hb;
    m = *(uint32_t*)&mb;
    if (want3) {
        float2 mf = __bfloat1622float2(mb);
        __nv_bfloat162 lb = __float22bfloat162_rn(make_float2(rx - mf.x, ry - mf.y));
        l = *(uint32_t*)&lb;
    } else {
        l = 0;
    }
}

#define LT (128 * 72)   // bf16 elements per limb tile (BK=64, stride 72)

// ---------------------------------------------------------------------------
// HMMA GEMM with IN-KERNEL bf16 limb split, BK=64 (12 barrier pairs vs 24).
// C[M,N] = A[M,K] @ B[N,K]^T (+bias). 128x128 tile, 256 threads, 2 CTAs/SM.
// ---------------------------------------------------------------------------
template<int NSPLIT>
__global__ __launch_bounds__(256, 2) void hmma_gemm_abt(
    const float* __restrict__ A, const float* __restrict__ B,
    const float* __restrict__ bias, float* __restrict__ C,
    int M, int N, int K)
{
    extern __shared__ __align__(16) char smem[];
    __nv_bfloat16* As = (__nv_bfloat16*)smem;
    __nv_bfloat16* Bs = As + NSPLIT * LT;

    const int tid  = threadIdx.x;
    const int lane = tid & 31;
    const int wid  = tid >> 5;
    const int wm   = wid >> 2;
    const int wn   = wid & 3;
    const int grp  = lane >> 2;
    const int tg   = lane & 3;
    const int bm0  = blockIdx.y * 128;
    const int bn0  = blockIdx.x * 128;

    float d[4][4][4];
#pragma unroll
    for (int am = 0; am < 4; am++)
#pragma unroll
        for (int an = 0; an < 4; an++)
#pragma unroll
            for (int r = 0; r < 4; r++) d[am][an][r] = 0.0f;

    const int NPR = (NSPLIT == 3) ? 6 : 3;
    const int PA[6] = {0, 0, 1, 0, 2, 1};
    const int PB[6] = {0, 1, 0, 2, 0, 1};

    for (int k0 = 0; k0 < K; k0 += 64) {
        __syncthreads();
#pragma unroll
        for (int half = 0; half < 2; half++) {
            const float* src = half ? (B + (size_t)bn0 * K) : (A + (size_t)bm0 * K);
            __nv_bfloat16* dst = half ? Bs : As;
#pragma unroll
            for (int it = 0; it < 4; it++) {
                const int f   = tid + it * 256;   // 0..1023
                const int row = f >> 3;           // 0..127
                const int c8  = f & 7;            // 8-float group (64 cols)
                const float* p = src + (size_t)row * K + k0 + c8 * 8;
                float4 v0 = *(const float4*)p;
                float4 v1 = *(const float4*)(p + 4);
                uint32_t h[4], m[4], l[4];
                split_pair_bf(v0.x, v0.y, h[0], m[0], l[0], NSPLIT == 3);
                split_pair_bf(v0.z, v0.w, h[1], m[1], l[1], NSPLIT == 3);
                split_pair_bf(v1.x, v1.y, h[2], m[2], l[2], NSPLIT == 3);
                split_pair_bf(v1.z, v1.w, h[3], m[3], l[3], NSPLIT == 3);
                const int base = row * 72 + c8 * 8;
#pragma unroll
                for (int j = 0; j < 4; j++) {
                    *(uint32_t*)&dst[0 * LT + base + j * 2] = h[j];
                    *(uint32_t*)&dst[1 * LT + base + j * 2] = m[j];
                    if (NSPLIT == 3)
                        *(uint32_t*)&dst[2 * LT + base + j * 2] = l[j];
                }
            }
        }
        __syncthreads();

#pragma unroll
        for (int ks = 0; ks < 4; ks++) {
#pragma unroll
            for (int p = 0; p < NPR; p++) {
                const int la = PA[p], lb = PB[p];
                uint32_t afr[4][4];
#pragma unroll
                for (int am = 0; am < 4; am++) {
                    const __nv_bfloat16* ap =
                        As + la * LT + (wm * 64 + am * 16 + grp) * 72 + ks * 16 + tg * 2;
                    afr[am][0] = *(const uint32_t*)ap;
                    afr[am][1] = *(const uint32_t*)(ap + 8 * 72);
                    afr[am][2] = *(const uint32_t*)(ap + 8);
                    afr[am][3] = *(const uint32_t*)(ap + 8 * 72 + 8);
                }
#pragma unroll
                for (int an = 0; an < 4; an++) {
                    const __nv_bfloat16* bp =
                        Bs + lb * LT + (wn * 32 + an * 8 + grp) * 72 + ks * 16 + tg * 2;
                    uint32_t bfr[2];
                    bfr[0] = *(const uint32_t*)bp;
                    bfr[1] = *(const uint32_t*)(bp + 8);
#pragma unroll
                    for (int am = 0; am < 4; am++)
                        mma_bf16(d[am][an], afr[am], bfr);
                }
            }
        }
    }

#pragma unroll
    for (int am = 0; am < 4; am++) {
        const int r0 = bm0 + wm * 64 + am * 16 + grp;
#pragma unroll
        for (int an = 0; an < 4; an++) {
            const int c0 = bn0 + wn * 32 + an * 8 + tg * 2;
            float bv0 = 0.0f, bv1 = 0.0f;
            if (bias) { bv0 = bias[c0]; bv1 = bias[c0 + 1]; }
            *(float2*)&C[(size_t)r0 * N + c0] =
                make_float2(d[am][an][0] + bv0, d[am][an][1] + bv1);
            *(float2*)&C[(size_t)(r0 + 8) * N + c0] =
                make_float2(d[am][an][2] + bv0, d[am][an][3] + bv1);
        }
    }
}

// ---------------------------------------------------------------------------
// HMMA GEMM on PRE-SPLIT bf16 limbs, BK=64 (for out-proj: A=ctx16, B=w216).
// ---------------------------------------------------------------------------
template<int NSPLIT>
__global__ __launch_bounds__(256, 2) void hmma_gemm_pre(
    const __nv_bfloat16* __restrict__ A, size_t sA,
    const __nv_bfloat16* __restrict__ B, size_t sB,
    const float* __restrict__ bias, float* __restrict__ C,
    int M, int N, int K)
{
    extern __shared__ __align__(16) char smem[];
    __nv_bfloat16* As = (__nv_bfloat16*)smem;
    __nv_bfloat16* Bs = As + NSPLIT * LT;

    const int tid  = threadIdx.x;
    const int lane = tid & 31;
    const int wid  = tid >> 5;
    const int wm   = wid >> 2;
    const int wn   = wid & 3;
    const int grp  = lane >> 2;
    const int tg   = lane & 3;
    const int bm0  = blockIdx.y * 128;
    const int bn0  = blockIdx.x * 128;

    float d[4][4][4];
#pragma unroll
    for (int am = 0; am < 4; am++)
#pragma unroll
        for (int an = 0; an < 4; an++)
#pragma unroll
            for (int r = 0; r < 4; r++) d[am][an][r] = 0.0f;

    const int NPR = (NSPLIT == 3) ? 6 : 3;
    const int PA[6] = {0, 0, 1, 0, 2, 1};
    const int PB[6] = {0, 1, 0, 2, 0, 1};

    for (int k0 = 0; k0 < K; k0 += 64) {
        __syncthreads();
#pragma unroll
        for (int half = 0; half < 2; half++) {
            const __nv_bfloat16* src = half ? (B + (size_t)bn0 * K) : (A + (size_t)bm0 * K);
            const size_t ps = half ? sB : sA;
            __nv_bfloat16* dst = half ? Bs : As;
#pragma unroll
            for (int it = 0; it < 4; it++) {
                const int f   = tid + it * 256;
                const int row = f >> 3;
                const int c8  = f & 7;
                const size_t go = (size_t)row * K + k0 + c8 * 8;
                const int   so = row * 72 + c8 * 8;
#pragma unroll
                for (int lb = 0; lb < NSPLIT; lb++) {
                    uint4 v = *(const uint4*)(src + lb * ps + go);
                    *(uint4*)&dst[lb * LT + so] = v;
                }
            }
        }
        __syncthreads();

#pragma unroll
        for (int ks = 0; ks < 4; ks++) {
#pragma unroll
            for (int p = 0; p < NPR; p++) {
                const int la = PA[p], lb = PB[p];
                uint32_t afr[4][4];
#pragma unroll
                for (int am = 0; am < 4; am++) {
                    const __nv_bfloat16* ap =
                        As + la * LT + (wm * 64 + am * 16 + grp) * 72 + ks * 16 + tg * 2;
                    afr[am][0] = *(const uint32_t*)ap;
                    afr[am][1] = *(const uint32_t*)(ap + 8 * 72);
                    afr[am][2] = *(const uint32_t*)(ap + 8);
                    afr[am][3] = *(const uint32_t*)(ap + 8 * 72 + 8);
                }
#pragma unroll
                for (int an = 0; an < 4; an++) {
                    const __nv_bfloat16* bp =
                        Bs + lb * LT + (wn * 32 + an * 8 + grp) * 72 + ks * 16 + tg * 2;
                    uint32_t bfr[2];
                    bfr[0] = *(const uint32_t*)bp;
                    bfr[1] = *(const uint32_t*)(bp + 8);
#pragma unroll
                    for (int am = 0; am < 4; am++)
                        mma_bf16(d[am][an], afr[am], bfr);
                }
            }
        }
    }

#pragma unroll
    for (int am = 0; am < 4; am++) {
        const int r0 = bm0 + wm * 64 + am * 16 + grp;
#pragma unroll
        for (int an = 0; an < 4; an++) {
            const int c0 = bn0 + wn * 32 + an * 8 + tg * 2;
            float bv0 = 0.0f, bv1 = 0.0f;
            if (bias) { bv0 = bias[c0]; bv1 = bias[c0 + 1]; }
            *(float2*)&C[(size_t)r0 * N + c0] =
                make_float2(d[am][an][0] + bv0, d[am][an][1] + bv1);
            *(float2*)&C[(size_t)(r0 + 8) * N + c0] =
                make_float2(d[am][an][2] + bv0, d[am][an][3] + bv1);
        }
    }
}

// ---------------------------------------------------------------------------
// Prep: fp32 -> NS bf16 limb planes (for out_w only; tiny).
// ---------------------------------------------------------------------------
template<int NS>
__global__ __launch_bounds__(256) void split_bf_kernel(
    const float* __restrict__ src, __nv_bfloat16* __restrict__ dst, size_t n)
{
    const size_t i = ((size_t)blockIdx.x * 256 + threadIdx.x) * 8;
    float4 v0 = *(const float4*)(src + i);
    float4 v1 = *(const float4*)(src + i + 4);
    uint32_t h[4], m[4], l[4];
    split_pair_bf(v0.x, v0.y, h[0], m[0], l[0], NS == 3);
    split_pair_bf(v0.z, v0.w, h[1], m[1], l[1], NS == 3);
    split_pair_bf(v1.x, v1.y, h[2], m[2], l[2], NS == 3);
    split_pair_bf(v1.z, v1.w, h[3], m[3], l[3], NS == 3);
    *(uint4*)(dst + i)     = make_uint4(h[0], h[1], h[2], h[3]);
    *(uint4*)(dst + n + i) = make_uint4(m[0], m[1], m[2], m[3]);
    if (NS == 3)
        *(uint4*)(dst + 2 * n + i) = make_uint4(l[0], l[1], l[2], l[3]);
}

// ---------------------------------------------------------------------------
// Prep K: fp32 -> fp16 hi/lo limbs, layout [limb][h][k][d]. (proven)
// ---------------------------------------------------------------------------
__global__ __launch_bounds__(256) void prep_k(
    const float* __restrict__ qkv, __half* __restrict__ k16)
{
    const int u  = blockIdx.x * 256 + threadIdx.x;
    const int hk = u >> 2, ch = u & 3;
    const int h = hk >> 12, k = hk & 4095;
    const float* src = qkv + (size_t)k * QKV_LD + EMB + h * HD + ch * 16;
    __half* dh = k16 + ((size_t)h * SEQ + k) * HD + ch * 16;

    uint32_t hi[8], lo[8];
#pragma unroll
    for (int j = 0; j < 4; j++) {
        float4 v = *(const float4*)(src + j * 4);
        split_h2(v.x, v.y, hi[j * 2], lo[j * 2]);
        split_h2(v.z, v.w, hi[j * 2 + 1], lo[j * 2 + 1]);
    }
    *(uint4*)dh       = make_uint4(hi[0], hi[1], hi[2], hi[3]);
    *(uint4*)(dh + 8) = make_uint4(hi[4], hi[5], hi[6], hi[7]);
    __half* dl = dh + LIMB;
    *(uint4*)dl       = make_uint4(lo[0], lo[1], lo[2], lo[3]);
    *(uint4*)(dl + 8) = make_uint4(lo[4], lo[5], lo[6], lo[7]);
}

// ---------------------------------------------------------------------------
// Prep V: split + transpose to [limb][h][c][k]. (proven)
// ---------------------------------------------------------------------------
__global__ __launch_bounds__(256) void prep_v(
    const float* __restrict__ qkv, __half* __restrict__ v16)
{
    __shared__ __align__(16) __half sv[2][64][80];
    const int h  = blockIdx.y, kb = blockIdx.x;
    const int t  = threadIdx.x;
    {
        const int k = t >> 2, ch = t & 3;
        const float* src = qkv + (size_t)(kb * 64 + k) * QKV_LD + 2 * EMB + h * HD + ch * 16;
#pragma unroll
        for (int j = 0; j < 16; j += 2) {
            float2 v = *(const float2*)(src + j);
            __half2 a = __floats2half2_rn(v.x, v.y);
            float2 f = __half22float2(a);
            __half2 r = __floats2half2_rn(v.x - f.x, v.y - f.y);
            const int c = ch * 16 + j;
            sv[0][c][k]     = __low2half(a);
            sv[0][c + 1][k] = __high2half(a);
            sv[1][c][k]     = __low2half(r);
            sv[1][c + 1][k] = __high2half(r);
        }
    }
    __syncthreads();
    {
        const int c = t >> 2, kc = t & 3;
        __half* dst = v16 + ((size_t)h * HD + c) * SEQ + kb * 64 + kc * 16;
#pragma unroll
        for (int j = 0; j < 2; j++) {
            *(uint4*)(dst + j * 8)        = *(const uint4*)&sv[0][c][kc * 16 + j * 8];
            *(uint4*)(dst + LIMB + j * 8) = *(const uint4*)&sv[1][c][kc * 16 + j * 8];
        }
    }
}

// ---------------------------------------------------------------------------
// HMMA flash attention, split-K x3, register-resident P (proven, unchanged).
// ---------------------------------------------------------------------------
#define SQH 0                    // Q hi  [128][72]
#define SQL (SQH + 128 * 72)     // Q lo
#define SKH (SQL + 128 * 72)     // K hi  [64 key][72 d]
#define SKL (SKH + 64 * 72)      // K lo
#define SVH (SKL + 64 * 72)      // V^T hi [64 c][72 k]
#define SVL (SVH + 64 * 72)      // V^T lo
#define ATTN_HALVES (SVL + 64 * 72)           // 36864
#define ATTN_SMEM_BYTES (ATTN_HALVES * 2)     // 73728

__global__ __launch_bounds__(256, 2) void attn_hmma(
    const float* __restrict__ qkv,
    const __half* __restrict__ k16, const __half* __restrict__ v16,
    float* __restrict__ opart, float* __restrict__ ml)
{
    extern __shared__ __align__(16) __half sh[];
    const int tid  = threadIdx.x;
    const int lane = tid & 31;
    const int wid  = tid >> 5;
    const int grp  = lane >> 2;
    const int tg   = lane & 3;
    const int h    = blockIdx.y;
    const int q0   = blockIdx.x * 128;
    const int sp   = blockIdx.z;

    const int kt0 = (sp == 0) ? 0 : (sp == 1 ? 22 : 43);
    const int kt1 = (sp == 0) ? 22 : (sp == 1 ? 43 : 64);

    // ---- Load Q tile, scale by 8*log2e, split into fp16 limbs ----
#pragma unroll
    for (int f = tid; f < 512; f += 256) {
        const int row = f >> 2, ch = f & 3;
        const float* p = qkv + (size_t)(q0 + row) * QKV_LD + h * HD + ch * 16;
        uint32_t hi[8], lo[8];
#pragma unroll
        for (int j = 0; j < 4; j++) {
            float4 v = *(const float4*)(p + j * 4);
            const float sc = 8.0f * LOG2E;
            split_h2(v.x * sc, v.y * sc, hi[j * 2], lo[j * 2]);
            split_h2(v.z * sc, v.w * sc, hi[j * 2 + 1], lo[j * 2 + 1]);
        }
        const int o = row * 72 + ch * 16;
        *(uint4*)&sh[SQH + o]     = make_uint4(hi[0], hi[1], hi[2], hi[3]);
        *(uint4*)&sh[SQH + o + 8] = make_uint4(hi[4], hi[5], hi[6], hi[7]);
        *(uint4*)&sh[SQL + o]     = make_uint4(lo[0], lo[1], lo[2], lo[3]);
        *(uint4*)&sh[SQL + o + 8] = make_uint4(lo[4], lo[5], lo[6], lo[7]);
    }

    const __half* kP = k16 + (size_t)h * SEQ * HD;
    const __half* vP = v16 + (size_t)h * HD * SEQ;

    int clt[4], crow[4], cseg[4];
#pragma unroll
    for (int i = 0; i < 4; i++) {
        const int g = tid + i * 256;
        clt[i]  = g >> 9;
        crow[i] = (g >> 3) & 63;
        cseg[i] = g & 7;
    }

    auto sts_chunk = [&](int base_h, int base_l, int i, uint4 v) {
        const int off = (base_h + (clt[i] ? (base_l - base_h) : 0))
                        + crow[i] * 72 + cseg[i] * 8;
        *(uint2*)&sh[off]     = make_uint2(v.x, v.y);
        *(uint2*)&sh[off + 4] = make_uint2(v.z, v.w);
    };

    // ---- Preload K(kt0) and V(kt0) ----
    {
        uint4 kc4[4], vc4[4];
#pragma unroll
        for (int i = 0; i < 4; i++) {
            kc4[i] = *(const uint4*)(kP + clt[i] * LIMB
                         + (size_t)(kt0 * 64 + crow[i]) * HD + cseg[i] * 8);
            vc4[i] = *(const uint4*)(vP + clt[i] * LIMB
                         + (size_t)crow[i] * SEQ + kt0 * 64 + cseg[i] * 8);
        }
#pragma unroll
        for (int i = 0; i < 4; i++) {
            sts_chunk(SKH, SKL, i, kc4[i]);
            sts_chunk(SVH, SVL, i, vc4[i]);
        }
    }
    __syncthreads();

    float m0 = -1e30f, m1 = -1e30f, l0 = 0.0f, l1 = 0.0f;
    float O[8][4];
#pragma unroll
    for (int nt = 0; nt < 8; nt++)
#pragma unroll
        for (int r = 0; r < 4; r++) O[nt][r] = 0.0f;

    const int qrow = (wid * 16 + grp) * 72 + tg * 2;

    for (int it = kt0; it < kt1; it++) {
        const int kt = it * 64;
        const bool pf = (it + 1) < kt1;

        uint4 kc4[4], vc4[4];
        if (pf) {
#pragma unroll
            for (int i = 0; i < 4; i++) {
                kc4[i] = *(const uint4*)(kP + clt[i] * LIMB
                             + (size_t)(kt + 64 + crow[i]) * HD + cseg[i] * 8);
                vc4[i] = *(const uint4*)(vP + clt[i] * LIMB
                             + (size_t)crow[i] * SEQ + kt + 64 + cseg[i] * 8);
            }
        }

        // ---- S = Q K^T (3 fp16 limb products) ----
        float s[8][4];
#pragma unroll
        for (int nt = 0; nt < 8; nt++)
#pragma unroll
            for (int r = 0; r < 4; r++) s[nt][r] = 0.0f;

#pragma unroll
        for (int ks = 0; ks < 4; ks++) {
            const int qa = qrow + ks * 16;
            uint32_t ah[4], al_[4];
            ah[0] = *(const uint32_t*)&sh[SQH + qa];
            ah[1] = *(const uint32_t*)&sh[SQH + qa + 8 * 72];
            ah[2] = *(const uint32_t*)&sh[SQH + qa + 8];
            ah[3] = *(const uint32_t*)&sh[SQH + qa + 8 * 72 + 8];
            al_[0] = *(const uint32_t*)&sh[SQL + qa];
            al_[1] = *(const uint32_t*)&sh[SQL + qa + 8 * 72];
            al_[2] = *(const uint32_t*)&sh[SQL + qa + 8];
            al_[3] = *(const uint32_t*)&sh[SQL + qa + 8 * 72 + 8];
#pragma unroll
            for (int nt = 0; nt < 8; nt++) {
                const int ka = (nt * 8 + grp) * 72 + ks * 16 + tg * 2;
                uint32_t kh[2], kl[2];
                kh[0] = *(const uint32_t*)&sh[SKH + ka];
                kh[1] = *(const uint32_t*)&sh[SKH + ka + 8];
                kl[0] = *(const uint32_t*)&sh[SKL + ka];
                kl[1] = *(const uint32_t*)&sh[SKL + ka + 8];
                mma_f16(s[nt], ah, kh);
                mma_f16(s[nt], al_, kh);
                mma_f16(s[nt], ah, kl);
            }
        }

        // ---- Online softmax (log2 domain) ----
        float mx0 = -1e30f, mx1 = -1e30f;
#pragma unroll
        for (int nt = 0; nt < 8; nt++) {
            mx0 = fmaxf(mx0, fmaxf(s[nt][0], s[nt][1]));
            mx1 = fmaxf(mx1, fmaxf(s[nt][2], s[nt][3]));
        }
        mx0 = fmaxf(mx0, __shfl_xor_sync(0xffffffffu, mx0, 1));
        mx0 = fmaxf(mx0, __shfl_xor_sync(0xffffffffu, mx0, 2));
        mx1 = fmaxf(mx1, __shfl_xor_sync(0xffffffffu, mx1, 1));
        mx1 = fmaxf(mx1, __shfl_xor_sync(0xffffffffu, mx1, 2));

        const float mn0 = fmaxf(m0, mx0), mn1 = fmaxf(m1, mx1);
        const float al0 = ex2f(m0 - mn0), al1 = ex2f(m1 - mn1);
        m0 = mn0; m1 = mn1;

        float sum0 = 0.0f, sum1 = 0.0f;
#pragma unroll
        for (int nt = 0; nt < 8; nt++) {
            s[nt][0] = ex2f(s[nt][0] - mn0); sum0 += s[nt][0];
            s[nt][1] = ex2f(s[nt][1] - mn0); sum0 += s[nt][1];
            s[nt][2] = ex2f(s[nt][2] - mn1); sum1 += s[nt][2];
            s[nt][3] = ex2f(s[nt][3] - mn1); sum1 += s[nt][3];
        }
        sum0 += __shfl_xor_sync(0xffffffffu, sum0, 1);
        sum0 += __shfl_xor_sync(0xffffffffu, sum0, 2);
        sum1 += __shfl_xor_sync(0xffffffffu, sum1, 1);
        sum1 += __shfl_xor_sync(0xffffffffu, sum1, 2);
        l0 = l0 * al0 + sum0;
        l1 = l1 * al1 + sum1;

#pragma unroll
        for (int nt = 0; nt < 8; nt++) {
            O[nt][0] *= al0; O[nt][1] *= al0;
            O[nt][2] *= al1; O[nt][3] *= al1;
        }

        // ---- O += P V: P packed from S fragments IN REGISTERS ----
#pragma unroll
        for (int kc = 0; kc < 4; kc++) {
            uint32_t ph[4], pl[4];
            split_h2(s[2 * kc][0],     s[2 * kc][1],     ph[0], pl[0]);
            split_h2(s[2 * kc][2],     s[2 * kc][3],     ph[1], pl[1]);
            split_h2(s[2 * kc + 1][0], s[2 * kc + 1][1], ph[2], pl[2]);
            split_h2(s[2 * kc + 1][2], s[2 * kc + 1][3], ph[3], pl[3]);
#pragma unroll
            for (int nt = 0; nt < 8; nt++) {
                const int va = (nt * 8 + grp) * 72 + kc * 16 + tg * 2;
                uint32_t vh[2], vl[2];
                vh[0] = *(const uint32_t*)&sh[SVH + va];
                vh[1] = *(const uint32_t*)&sh[SVH + va + 8];
                vl[0] = *(const uint32_t*)&sh[SVL + va];
                vl[1] = *(const uint32_t*)&sh[SVL + va + 8];
                mma_f16(O[nt], ph, vh);
                mma_f16(O[nt], pl, vh);
                mma_f16(O[nt], ph, vl);
            }
        }

        if (pf) {
            __syncthreads();
#pragma unroll
            for (int i = 0; i < 4; i++) {
                sts_chunk(SKH, SKL, i, kc4[i]);
                sts_chunk(SVH, SVL, i, vc4[i]);
            }
            __syncthreads();
        }
    }

    // ---- Write UNNORMALIZED partial O + (m,l) per row ----
    const int r0 = q0 + wid * 16 + grp;
    float* op = opart + (size_t)sp * SEQ * EMB;
#pragma unroll
    for (int nt = 0; nt < 8; nt++) {
        const int c = h * HD + nt * 8 + tg * 2;
        *(float2*)&op[(size_t)r0 * EMB + c]       = make_float2(O[nt][0], O[nt][1]);
        *(float2*)&op[(size_t)(r0 + 8) * EMB + c] = make_float2(O[nt][2], O[nt][3]);
    }
    if (tg == 0) {
        float* mlp = ml + (((size_t)sp * HEADS + h) * SEQ) * 2;
        *(float2*)&mlp[(size_t)r0 * 2]       = make_float2(m0, l0);
        *(float2*)&mlp[(size_t)(r0 + 8) * 2] = make_float2(m1, l1);
    }
}

// ---------------------------------------------------------------------------
// Merge the 3 split-K partials; emit ctx as 2 bf16 limb planes.
// ---------------------------------------------------------------------------
__global__ __launch_bounds__(256) void merge_kernel(
    const float* __restrict__ part, const float* __restrict__ ml,
    __nv_bfloat16* __restrict__ ctx16)
{
    const int idx = blockIdx.x * 256 + threadIdx.x;
    const int row = idx / (EMB / 4);
    const int c4  = idx % (EMB / 4);
    const int h   = (c4 * 4) >> 6;

    float m[NSPLIT_K], lv[NSPLIT_K];
#pragma unroll
    for (int p = 0; p < NSPLIT_K; p++) {
        float2 v = *(const float2*)(ml + (((size_t)p * HEADS + h) * SEQ + row) * 2);
        m[p] = v.x; lv[p] = v.y;
    }
    const float M = fmaxf(m[0], fmaxf(m[1], m[2]));
    const float w0 = ex2f(m[0] - M), w1 = ex2f(m[1] - M), w2 = ex2f(m[2] - M);
    const float inv = 1.0f / (lv[0] * w0 + lv[1] * w1 + lv[2] * w2);

    const size_t off = (size_t)row * EMB + c4 * 4;
    float4 a = *(const float4*)(part + off);
    float4 b = *(const float4*)(part + (size_t)SEQ * EMB + off);
    float4 c = *(const float4*)(part + 2 * (size_t)SEQ * EMB + off);
    float4 o;
    o.x = (a.x * w0 + b.x * w1 + c.x * w2) * inv;
    o.y = (a.y * w0 + b.y * w1 + c.y * w2) * inv;
    o.z = (a.z * w0 + b.z * w1 + c.z * w2) * inv;
    o.w = (a.w * w0 + b.w * w1 + c.w * w2) * inv;

    uint32_t h0, m0_, l0_, h1, m1_, l1_;
    split_pair_bf(o.x, o.y, h0, m0_, l0_, false);
    split_pair_bf(o.z, o.w, h1, m1_, l1_, false);
    *(uint2*)(ctx16 + off)                     = make_uint2(h0, h1);
    *(uint2*)(ctx16 + (size_t)SEQ * EMB + off) = make_uint2(m0_, m1_);
}

// ---------------------------------------------------------------------------
extern "C" void kernel_launch(void* const* d_in, const int* in_sizes, int n_in,
                              void* d_out, int out_size)
{
    (void)in_sizes; (void)n_in; (void)out_size;
    const float* x     = (const float*)d_in[0];   // [1,4096,768]
    const float* qkv_w = (const float*)d_in[1];   // [2304,768]
    const float* out_w = (const float*)d_in[2];   // [768,768]
    const float* out_b = (const float*)d_in[3];   // [768]
    float* out = (float*)d_out;                   // [1,4096,768]

    float *qkv = nullptr, *part = nullptr, *ml = nullptr;
    __half *k16 = nullptr, *v16 = nullptr;
    __nv_bfloat16 *w216 = nullptr, *ctx16 = nullptr;
    cudaGetSymbolAddress((void**)&qkv, g_qkv);
    cudaGetSymbolAddress((void**)&k16, g_k16);
    cudaGetSymbolAddress((void**)&v16, g_v16);
    cudaGetSymbolAddress((void**)&part, g_part);
    cudaGetSymbolAddress((void**)&ml, g_ml);
    cudaGetSymbolAddress((void**)&w216, g_w216);
    cudaGetSymbolAddress((void**)&ctx16, g_ctx16);

    // 0) Pre-split out_w only (tiny)
    split_bf_kernel<2><<<(EMB * EMB) / 2048, 256>>>(out_w, w216, (size_t)EMB * EMB);

    // 1) QKV projection (HMMA bf16x3, in-kernel split, BK=64)
    const int smem3 = 6 * LT * (int)sizeof(__nv_bfloat16);   // 110592
    cudaFuncSetAttribute(hmma_gemm_abt<3>,
                         cudaFuncAttributeMaxDynamicSharedMemorySize, smem3);
    hmma_gemm_abt<3><<<dim3(QKV_LD / 128, SEQ / 128), 256, smem3>>>(
        x, qkv_w, nullptr, qkv, SEQ, QKV_LD, EMB);

    // 2) K/V fp16 limb pre-split
    prep_k<<<768, 256>>>(qkv, k16);
    prep_v<<<dim3(64, HEADS), 256>>>(qkv, v16);

    // 3) HMMA flash attention, split-K x3, register-resident P
    cudaFuncSetAttribute(attn_hmma,
                         cudaFuncAttributeMaxDynamicSharedMemorySize, ATTN_SMEM_BYTES);
    attn_hmma<<<dim3(SEQ / 128, HEADS, NSPLIT_K), 256, ATTN_SMEM_BYTES>>>(
        qkv, k16, v16, part, ml);

    // 4) Merge partials -> ctx bf16 limbs
    merge_kernel<<<(SEQ * EMB / 4) / 256, 256>>>(part, ml, ctx16);

    // 5) Output projection + bias (HMMA bf16x2, pre-split, BK=64)
    const int smem2 = 4 * LT * (int)sizeof(__nv_bfloat16);   // 73728
    cudaFuncSetAttribute(hmma_gemm_pre<2>,
                         cudaFuncAttributeMaxDynamicSharedMemorySize, smem2);
    hmma_gemm_pre<2><<<dim3(EMB / 128, SEQ / 128), 256, smem2>>>(
        ctx16, (size_t)SEQ * EMB, w216, (size_t)EMB * EMB,
        out_b, out, SEQ, EMB, EMB);
}

// round 17
// speedup vs baseline: 1.0729x; 1.0278x over previous
#include <cuda_runtime.h>
#include <cuda_bf16.h>
#include <cuda_fp16.h>
#include <math.h>
#include <stdint.h>

#define EMB 768
#define HEADS 12
#define HD 64
#define SEQ 4096
#define QKV_LD (3 * EMB)   // 2304
#define LIMB ((size_t)HEADS * SEQ * HD)   // halves per K/V limb plane
#define LOG2E 1.4426950408889634f
#define NSPLIT_K 3

// Scratch (static device globals — no allocation)
__device__ __align__(16) float g_qkv[(size_t)SEQ * QKV_LD];        // Q|K|V fp32
__device__ __align__(16) __half g_k16[2 * HEADS * SEQ * HD];       // [limb][h][k][d]
__device__ __align__(16) __half g_v16[2 * HEADS * SEQ * HD];       // [limb][h][c][k]
__device__ __align__(16) float g_part[(size_t)NSPLIT_K * SEQ * EMB];
__device__ __align__(16) float g_ml[(size_t)NSPLIT_K * HEADS * SEQ * 2];
__device__ __align__(16) __nv_bfloat16 g_w216[2 * (size_t)EMB * EMB];
__device__ __align__(16) __nv_bfloat16 g_ctx16[2 * (size_t)SEQ * EMB];

// ---------------------------------------------------------------------------
// HMMA + ldmatrix helpers (all supported on base sm_103 target)
// ---------------------------------------------------------------------------
__device__ __forceinline__ void mma_bf16(float* d, const uint32_t* a, const uint32_t* b) {
    asm volatile(
        "mma.sync.aligned.m16n8k16.row.col.f32.bf16.bf16.f32 "
        "{%0,%1,%2,%3}, {%4,%5,%6,%7}, {%8,%9}, {%0,%1,%2,%3};"
        : "+f"(d[0]), "+f"(d[1]), "+f"(d[2]), "+f"(d[3])
        : "r"(a[0]), "r"(a[1]), "r"(a[2]), "r"(a[3]), "r"(b[0]), "r"(b[1]));
}
__device__ __forceinline__ void mma_f16(float* d, const uint32_t* a, const uint32_t* b) {
    asm volatile(
        "mma.sync.aligned.m16n8k16.row.col.f32.f16.f16.f32 "
        "{%0,%1,%2,%3}, {%4,%5,%6,%7}, {%8,%9}, {%0,%1,%2,%3};"
        : "+f"(d[0]), "+f"(d[1]), "+f"(d[2]), "+f"(d[3])
        : "r"(a[0]), "r"(a[1]), "r"(a[2]), "r"(a[3]), "r"(b[0]), "r"(b[1]));
}
__device__ __forceinline__ uint32_t smem_u32(const void* p) {
    uint32_t a;
    asm("{ .reg .u64 t; cvta.to.shared.u64 t, %1; cvt.u32.u64 %0, t; }"
        : "=r"(a) : "l"(p));
    return a;
}
__device__ __forceinline__ void ldsm_x4(uint32_t addr, uint32_t* r) {
    asm volatile("ldmatrix.sync.aligned.m8n8.x4.shared.b16 {%0,%1,%2,%3}, [%4];"
                 : "=r"(r[0]), "=r"(r[1]), "=r"(r[2]), "=r"(r[3]) : "r"(addr));
}
__device__ __forceinline__ void ldsm_x2(uint32_t addr, uint32_t* r) {
    asm volatile("ldmatrix.sync.aligned.m8n8.x2.shared.b16 {%0,%1}, [%2];"
                 : "=r"(r[0]), "=r"(r[1]) : "r"(addr));
}
__device__ __forceinline__ uint32_t h2bits(__half2 h) { return *(uint32_t*)&h; }
__device__ __forceinline__ float ex2f(float x) {
    float r; asm("ex2.approx.ftz.f32 %0, %1;" : "=f"(r) : "f"(x)); return r;
}

// fp32 pair -> fp16 hi/lo limbs (packed f16x2: x -> low half)
__device__ __forceinline__ void split_h2(float x, float y, uint32_t& hi, uint32_t& lo) {
    __half2 h = __floats2half2_rn(x, y);
    float2 f = __half22float2(h);
    __half2 l = __floats2half2_rn(x - f.x, y - f.y);
    hi = h2bits(h);
    lo = h2bits(l);
}

// fp32 pair -> bf16 limb split
__device__ __forceinline__ void split_pair_bf(
    float x, float y, uint32_t& h, uint32_t& m, uint32_t& l, bool want3)
{
    __nv_bfloat162 hb = __float22bfloat162_rn(make_float2(x, y));
    float2 hf = __bfloat1622float2(hb);
    float rx = x - hf.x, ry = y - hf.y;
    __nv_bfloat162 mb = __float22bfloat162_rn(make_float2(rx, ry));
    h = *(uint32_t*)&hb;
    m = *(uint32_t*)&mb;
    if (want3) {
        float2 mf = __bfloat1622float2(mb);
        __nv_bfloat162 lb = __float22bfloat162_rn(make_float2(rx - mf.x, ry - mf.y));
        l = *(uint32_t*)&lb;
    } else {
        l = 0;
    }
}

#define LT (128 * 72)   // bf16 elements per limb tile (BK=64, stride 72)

// ---------------------------------------------------------------------------
// HMMA GEMM with IN-KERNEL bf16 limb split, BK=64 (proven round 16).
// ---------------------------------------------------------------------------
template<int NSPLIT>
__global__ __launch_bounds__(256, 2) void hmma_gemm_abt(
    const float* __restrict__ A, const float* __restrict__ B,
    const float* __restrict__ bias, float* __restrict__ C,
    int M, int N, int K)
{
    extern __shared__ __align__(16) char smem[];
    __nv_bfloat16* As = (__nv_bfloat16*)smem;
    __nv_bfloat16* Bs = As + NSPLIT * LT;

    const int tid  = threadIdx.x;
    const int lane = tid & 31;
    const int wid  = tid >> 5;
    const int wm   = wid >> 2;
    const int wn   = wid & 3;
    const int grp  = lane >> 2;
    const int tg   = lane & 3;
    const int bm0  = blockIdx.y * 128;
    const int bn0  = blockIdx.x * 128;

    float d[4][4][4];
#pragma unroll
    for (int am = 0; am < 4; am++)
#pragma unroll
        for (int an = 0; an < 4; an++)
#pragma unroll
            for (int r = 0; r < 4; r++) d[am][an][r] = 0.0f;

    const int NPR = (NSPLIT == 3) ? 6 : 3;
    const int PA[6] = {0, 0, 1, 0, 2, 1};
    const int PB[6] = {0, 1, 0, 2, 0, 1};

    for (int k0 = 0; k0 < K; k0 += 64) {
        __syncthreads();
#pragma unroll
        for (int half = 0; half < 2; half++) {
            const float* src = half ? (B + (size_t)bn0 * K) : (A + (size_t)bm0 * K);
            __nv_bfloat16* dst = half ? Bs : As;
#pragma unroll
            for (int it = 0; it < 4; it++) {
                const int f   = tid + it * 256;
                const int row = f >> 3;
                const int c8  = f & 7;
                const float* p = src + (size_t)row * K + k0 + c8 * 8;
                float4 v0 = *(const float4*)p;
                float4 v1 = *(const float4*)(p + 4);
                uint32_t h[4], m[4], l[4];
                split_pair_bf(v0.x, v0.y, h[0], m[0], l[0], NSPLIT == 3);
                split_pair_bf(v0.z, v0.w, h[1], m[1], l[1], NSPLIT == 3);
                split_pair_bf(v1.x, v1.y, h[2], m[2], l[2], NSPLIT == 3);
                split_pair_bf(v1.z, v1.w, h[3], m[3], l[3], NSPLIT == 3);
                const int base = row * 72 + c8 * 8;
#pragma unroll
                for (int j = 0; j < 4; j++) {
                    *(uint32_t*)&dst[0 * LT + base + j * 2] = h[j];
                    *(uint32_t*)&dst[1 * LT + base + j * 2] = m[j];
                    if (NSPLIT == 3)
                        *(uint32_t*)&dst[2 * LT + base + j * 2] = l[j];
                }
            }
        }
        __syncthreads();

#pragma unroll
        for (int ks = 0; ks < 4; ks++) {
#pragma unroll
            for (int p = 0; p < NPR; p++) {
                const int la = PA[p], lb = PB[p];
                uint32_t afr[4][4];
#pragma unroll
                for (int am = 0; am < 4; am++) {
                    const __nv_bfloat16* ap =
                        As + la * LT + (wm * 64 + am * 16 + grp) * 72 + ks * 16 + tg * 2;
                    afr[am][0] = *(const uint32_t*)ap;
                    afr[am][1] = *(const uint32_t*)(ap + 8 * 72);
                    afr[am][2] = *(const uint32_t*)(ap + 8);
                    afr[am][3] = *(const uint32_t*)(ap + 8 * 72 + 8);
                }
#pragma unroll
                for (int an = 0; an < 4; an++) {
                    const __nv_bfloat16* bp =
                        Bs + lb * LT + (wn * 32 + an * 8 + grp) * 72 + ks * 16 + tg * 2;
                    uint32_t bfr[2];
                    bfr[0] = *(const uint32_t*)bp;
                    bfr[1] = *(const uint32_t*)(bp + 8);
#pragma unroll
                    for (int am = 0; am < 4; am++)
                        mma_bf16(d[am][an], afr[am], bfr);
                }
            }
        }
    }

#pragma unroll
    for (int am = 0; am < 4; am++) {
        const int r0 = bm0 + wm * 64 + am * 16 + grp;
#pragma unroll
        for (int an = 0; an < 4; an++) {
            const int c0 = bn0 + wn * 32 + an * 8 + tg * 2;
            float bv0 = 0.0f, bv1 = 0.0f;
            if (bias) { bv0 = bias[c0]; bv1 = bias[c0 + 1]; }
            *(float2*)&C[(size_t)r0 * N + c0] =
                make_float2(d[am][an][0] + bv0, d[am][an][1] + bv1);
            *(float2*)&C[(size_t)(r0 + 8) * N + c0] =
                make_float2(d[am][an][2] + bv0, d[am][an][3] + bv1);
        }
    }
}

// ---------------------------------------------------------------------------
// HMMA GEMM on PRE-SPLIT bf16 limbs, BK=64 (out-proj).
// ---------------------------------------------------------------------------
template<int NSPLIT>
__global__ __launch_bounds__(256, 2) void hmma_gemm_pre(
    const __nv_bfloat16* __restrict__ A, size_t sA,
    const __nv_bfloat16* __restrict__ B, size_t sB,
    const float* __restrict__ bias, float* __restrict__ C,
    int M, int N, int K)
{
    extern __shared__ __align__(16) char smem[];
    __nv_bfloat16* As = (__nv_bfloat16*)smem;
    __nv_bfloat16* Bs = As + NSPLIT * LT;

    const int tid  = threadIdx.x;
    const int lane = tid & 31;
    const int wid  = tid >> 5;
    const int wm   = wid >> 2;
    const int wn   = wid & 3;
    const int grp  = lane >> 2;
    const int tg   = lane & 3;
    const int bm0  = blockIdx.y * 128;
    const int bn0  = blockIdx.x * 128;

    float d[4][4][4];
#pragma unroll
    for (int am = 0; am < 4; am++)
#pragma unroll
        for (int an = 0; an < 4; an++)
#pragma unroll
            for (int r = 0; r < 4; r++) d[am][an][r] = 0.0f;

    const int NPR = (NSPLIT == 3) ? 6 : 3;
    const int PA[6] = {0, 0, 1, 0, 2, 1};
    const int PB[6] = {0, 1, 0, 2, 0, 1};

    for (int k0 = 0; k0 < K; k0 += 64) {
        __syncthreads();
#pragma unroll
        for (int half = 0; half < 2; half++) {
            const __nv_bfloat16* src = half ? (B + (size_t)bn0 * K) : (A + (size_t)bm0 * K);
            const size_t ps = half ? sB : sA;
            __nv_bfloat16* dst = half ? Bs : As;
#pragma unroll
            for (int it = 0; it < 4; it++) {
                const int f   = tid + it * 256;
                const int row = f >> 3;
                const int c8  = f & 7;
                const size_t go = (size_t)row * K + k0 + c8 * 8;
                const int   so = row * 72 + c8 * 8;
#pragma unroll
                for (int lb = 0; lb < NSPLIT; lb++) {
                    uint4 v = *(const uint4*)(src + lb * ps + go);
                    *(uint4*)&dst[lb * LT + so] = v;
                }
            }
        }
        __syncthreads();

#pragma unroll
        for (int ks = 0; ks < 4; ks++) {
#pragma unroll
            for (int p = 0; p < NPR; p++) {
                const int la = PA[p], lb = PB[p];
                uint32_t afr[4][4];
#pragma unroll
                for (int am = 0; am < 4; am++) {
                    const __nv_bfloat16* ap =
                        As + la * LT + (wm * 64 + am * 16 + grp) * 72 + ks * 16 + tg * 2;
                    afr[am][0] = *(const uint32_t*)ap;
                    afr[am][1] = *(const uint32_t*)(ap + 8 * 72);
                    afr[am][2] = *(const uint32_t*)(ap + 8);
                    afr[am][3] = *(const uint32_t*)(ap + 8 * 72 + 8);
                }
#pragma unroll
                for (int an = 0; an < 4; an++) {
                    const __nv_bfloat16* bp =
                        Bs + lb * LT + (wn * 32 + an * 8 + grp) * 72 + ks * 16 + tg * 2;
                    uint32_t bfr[2];
                    bfr[0] = *(const uint32_t*)bp;
                    bfr[1] = *(const uint32_t*)(bp + 8);
#pragma unroll
                    for (int am = 0; am < 4; am++)
                        mma_bf16(d[am][an], afr[am], bfr);
                }
            }
        }
    }

#pragma unroll
    for (int am = 0; am < 4; am++) {
        const int r0 = bm0 + wm * 64 + am * 16 + grp;
#pragma unroll
        for (int an = 0; an < 4; an++) {
            const int c0 = bn0 + wn * 32 + an * 8 + tg * 2;
            float bv0 = 0.0f, bv1 = 0.0f;
            if (bias) { bv0 = bias[c0]; bv1 = bias[c0 + 1]; }
            *(float2*)&C[(size_t)r0 * N + c0] =
                make_float2(d[am][an][0] + bv0, d[am][an][1] + bv1);
            *(float2*)&C[(size_t)(r0 + 8) * N + c0] =
                make_float2(d[am][an][2] + bv0, d[am][an][3] + bv1);
        }
    }
}

// ---------------------------------------------------------------------------
// Prep: fp32 -> NS bf16 limb planes (for out_w only; tiny).
// ---------------------------------------------------------------------------
template<int NS>
__global__ __launch_bounds__(256) void split_bf_kernel(
    const float* __restrict__ src, __nv_bfloat16* __restrict__ dst, size_t n)
{
    const size_t i = ((size_t)blockIdx.x * 256 + threadIdx.x) * 8;
    float4 v0 = *(const float4*)(src + i);
    float4 v1 = *(const float4*)(src + i + 4);
    uint32_t h[4], m[4], l[4];
    split_pair_bf(v0.x, v0.y, h[0], m[0], l[0], NS == 3);
    split_pair_bf(v0.z, v0.w, h[1], m[1], l[1], NS == 3);
    split_pair_bf(v1.x, v1.y, h[2], m[2], l[2], NS == 3);
    split_pair_bf(v1.z, v1.w, h[3], m[3], l[3], NS == 3);
    *(uint4*)(dst + i)     = make_uint4(h[0], h[1], h[2], h[3]);
    *(uint4*)(dst + n + i) = make_uint4(m[0], m[1], m[2], m[3]);
    if (NS == 3)
        *(uint4*)(dst + 2 * n + i) = make_uint4(l[0], l[1], l[2], l[3]);
}

// ---------------------------------------------------------------------------
// Prep K: fp32 -> fp16 hi/lo limbs, layout [limb][h][k][d]. (proven)
// ---------------------------------------------------------------------------
__global__ __launch_bounds__(256) void prep_k(
    const float* __restrict__ qkv, __half* __restrict__ k16)
{
    const int u  = blockIdx.x * 256 + threadIdx.x;
    const int hk = u >> 2, ch = u & 3;
    const int h = hk >> 12, k = hk & 4095;
    const float* src = qkv + (size_t)k * QKV_LD + EMB + h * HD + ch * 16;
    __half* dh = k16 + ((size_t)h * SEQ + k) * HD + ch * 16;

    uint32_t hi[8], lo[8];
#pragma unroll
    for (int j = 0; j < 4; j++) {
        float4 v = *(const float4*)(src + j * 4);
        split_h2(v.x, v.y, hi[j * 2], lo[j * 2]);
        split_h2(v.z, v.w, hi[j * 2 + 1], lo[j * 2 + 1]);
    }
    *(uint4*)dh       = make_uint4(hi[0], hi[1], hi[2], hi[3]);
    *(uint4*)(dh + 8) = make_uint4(hi[4], hi[5], hi[6], hi[7]);
    __half* dl = dh + LIMB;
    *(uint4*)dl       = make_uint4(lo[0], lo[1], lo[2], lo[3]);
    *(uint4*)(dl + 8) = make_uint4(lo[4], lo[5], lo[6], lo[7]);
}

// ---------------------------------------------------------------------------
// Prep V: split + transpose to [limb][h][c][k]. (proven)
// ---------------------------------------------------------------------------
__global__ __launch_bounds__(256) void prep_v(
    const float* __restrict__ qkv, __half* __restrict__ v16)
{
    __shared__ __align__(16) __half sv[2][64][80];
    const int h  = blockIdx.y, kb = blockIdx.x;
    const int t  = threadIdx.x;
    {
        const int k = t >> 2, ch = t & 3;
        const float* src = qkv + (size_t)(kb * 64 + k) * QKV_LD + 2 * EMB + h * HD + ch * 16;
#pragma unroll
        for (int j = 0; j < 16; j += 2) {
            float2 v = *(const float2*)(src + j);
            __half2 a = __floats2half2_rn(v.x, v.y);
            float2 f = __half22float2(a);
            __half2 r = __floats2half2_rn(v.x - f.x, v.y - f.y);
            const int c = ch * 16 + j;
            sv[0][c][k]     = __low2half(a);
            sv[0][c + 1][k] = __high2half(a);
            sv[1][c][k]     = __low2half(r);
            sv[1][c + 1][k] = __high2half(r);
        }
    }
    __syncthreads();
    {
        const int c = t >> 2, kc = t & 3;
        __half* dst = v16 + ((size_t)h * HD + c) * SEQ + kb * 64 + kc * 16;
#pragma unroll
        for (int j = 0; j < 2; j++) {
            *(uint4*)(dst + j * 8)        = *(const uint4*)&sv[0][c][kc * 16 + j * 8];
            *(uint4*)(dst + LIMB + j * 8) = *(const uint4*)&sv[1][c][kc * 16 + j * 8];
        }
    }
}

// ---------------------------------------------------------------------------
// HMMA flash attention, split-K x3, register-resident P, LDMATRIX fragment
// loads (Q via x4, K/V via x2) — same bytes, 2-4x fewer shared-pipe issues.
// ---------------------------------------------------------------------------
#define SQH 0                    // Q hi  [128][72]
#define SQL (SQH + 128 * 72)     // Q lo
#define SKH (SQL + 128 * 72)     // K hi  [64 key][72 d]
#define SKL (SKH + 64 * 72)      // K lo
#define SVH (SKL + 64 * 72)      // V^T hi [64 c][72 k]
#define SVL (SVH + 64 * 72)      // V^T lo
#define ATTN_HALVES (SVL + 64 * 72)           // 36864
#define ATTN_SMEM_BYTES (ATTN_HALVES * 2)     // 73728

__global__ __launch_bounds__(256, 2) void attn_hmma(
    const float* __restrict__ qkv,
    const __half* __restrict__ k16, const __half* __restrict__ v16,
    float* __restrict__ opart, float* __restrict__ ml)
{
    extern __shared__ __align__(16) __half sh[];
    const int tid  = threadIdx.x;
    const int lane = tid & 31;
    const int wid  = tid >> 5;
    const int grp  = lane >> 2;
    const int tg   = lane & 3;
    const int h    = blockIdx.y;
    const int q0   = blockIdx.x * 128;
    const int sp   = blockIdx.z;

    const int kt0 = (sp == 0) ? 0 : (sp == 1 ? 22 : 43);
    const int kt1 = (sp == 0) ? 22 : (sp == 1 ? 43 : 64);

    // ---- Load Q tile, scale by 8*log2e, split into fp16 limbs ----
#pragma unroll
    for (int f = tid; f < 512; f += 256) {
        const int row = f >> 2, ch = f & 3;
        const float* p = qkv + (size_t)(q0 + row) * QKV_LD + h * HD + ch * 16;
        uint32_t hi[8], lo[8];
#pragma unroll
        for (int j = 0; j < 4; j++) {
            float4 v = *(const float4*)(p + j * 4);
            const float sc = 8.0f * LOG2E;
            split_h2(v.x * sc, v.y * sc, hi[j * 2], lo[j * 2]);
            split_h2(v.z * sc, v.w * sc, hi[j * 2 + 1], lo[j * 2 + 1]);
        }
        const int o = row * 72 + ch * 16;
        *(uint4*)&sh[SQH + o]     = make_uint4(hi[0], hi[1], hi[2], hi[3]);
        *(uint4*)&sh[SQH + o + 8] = make_uint4(hi[4], hi[5], hi[6], hi[7]);
        *(uint4*)&sh[SQL + o]     = make_uint4(lo[0], lo[1], lo[2], lo[3]);
        *(uint4*)&sh[SQL + o + 8] = make_uint4(lo[4], lo[5], lo[6], lo[7]);
    }

    const __half* kP = k16 + (size_t)h * SEQ * HD;
    const __half* vP = v16 + (size_t)h * HD * SEQ;

    int clt[4], crow[4], cseg[4];
#pragma unroll
    for (int i = 0; i < 4; i++) {
        const int g = tid + i * 256;
        clt[i]  = g >> 9;
        crow[i] = (g >> 3) & 63;
        cseg[i] = g & 7;
    }

    auto sts_chunk = [&](int base_h, int base_l, int i, uint4 v) {
        const int off = (base_h + (clt[i] ? (base_l - base_h) : 0))
                        + crow[i] * 72 + cseg[i] * 8;
        *(uint2*)&sh[off]     = make_uint2(v.x, v.y);
        *(uint2*)&sh[off + 4] = make_uint2(v.z, v.w);
    };

    // ---- ldmatrix base addresses (bytes) ----
    const uint32_t sb = smem_u32(sh);
    // A-frag (Q): lanes 0-7 tile rows 0-7 col 0; 8-15 rows 8-15 col 0;
    //             16-23 rows 0-7 col 8; 24-31 rows 8-15 col 8.
    const uint32_t qoff =
        ((wid * 16 + ((lane >> 3) & 1) * 8 + (lane & 7)) * 72 + ((lane >> 4) & 1) * 8) * 2;
    const uint32_t qa_h = sb + SQH * 2 + qoff;
    const uint32_t qa_l = sb + SQL * 2 + qoff;
    // B-frag (K/V): x2 uses lanes 0-15; lanes 16+ mirror lane&15.
    const int bl = lane & 15;
    const uint32_t boff = ((bl & 7) * 72 + ((bl >> 3) & 1) * 8) * 2;
    const uint32_t ka_h = sb + SKH * 2 + boff;
    const uint32_t ka_l = sb + SKL * 2 + boff;
    const uint32_t va_h = sb + SVH * 2 + boff;
    const uint32_t va_l = sb + SVL * 2 + boff;

    // ---- Preload K(kt0) and V(kt0) ----
    {
        uint4 kc4[4], vc4[4];
#pragma unroll
        for (int i = 0; i < 4; i++) {
            kc4[i] = *(const uint4*)(kP + clt[i] * LIMB
                         + (size_t)(kt0 * 64 + crow[i]) * HD + cseg[i] * 8);
            vc4[i] = *(const uint4*)(vP + clt[i] * LIMB
                         + (size_t)crow[i] * SEQ + kt0 * 64 + cseg[i] * 8);
        }
#pragma unroll
        for (int i = 0; i < 4; i++) {
            sts_chunk(SKH, SKL, i, kc4[i]);
            sts_chunk(SVH, SVL, i, vc4[i]);
        }
    }
    __syncthreads();

    float m0 = -1e30f, m1 = -1e30f, l0 = 0.0f, l1 = 0.0f;
    float O[8][4];
#pragma unroll
    for (int nt = 0; nt < 8; nt++)
#pragma unroll
        for (int r = 0; r < 4; r++) O[nt][r] = 0.0f;

    for (int it = kt0; it < kt1; it++) {
        const int kt = it * 64;
        const bool pf = (it + 1) < kt1;

        uint4 kc4[4], vc4[4];
        if (pf) {
#pragma unroll
            for (int i = 0; i < 4; i++) {
                kc4[i] = *(const uint4*)(kP + clt[i] * LIMB
                             + (size_t)(kt + 64 + crow[i]) * HD + cseg[i] * 8);
                vc4[i] = *(const uint4*)(vP + clt[i] * LIMB
                             + (size_t)crow[i] * SEQ + kt + 64 + cseg[i] * 8);
            }
        }

        // ---- S = Q K^T (3 fp16 limb products, ldmatrix loads) ----
        float s[8][4];
#pragma unroll
        for (int nt = 0; nt < 8; nt++)
#pragma unroll
            for (int r = 0; r < 4; r++) s[nt][r] = 0.0f;

#pragma unroll
        for (int ks = 0; ks < 4; ks++) {
            uint32_t ah[4], al_[4];
            ldsm_x4(qa_h + ks * 32, ah);
            ldsm_x4(qa_l + ks * 32, al_);
#pragma unroll
            for (int nt = 0; nt < 8; nt++) {
                uint32_t kh[2], kl[2];
                ldsm_x2(ka_h + nt * 1152 + ks * 32, kh);
                ldsm_x2(ka_l + nt * 1152 + ks * 32, kl);
                mma_f16(s[nt], ah, kh);
                mma_f16(s[nt], al_, kh);
                mma_f16(s[nt], ah, kl);
            }
        }

        // ---- Online softmax (log2 domain) ----
        float mx0 = -1e30f, mx1 = -1e30f;
#pragma unroll
        for (int nt = 0; nt < 8; nt++) {
            mx0 = fmaxf(mx0, fmaxf(s[nt][0], s[nt][1]));
            mx1 = fmaxf(mx1, fmaxf(s[nt][2], s[nt][3]));
        }
        mx0 = fmaxf(mx0, __shfl_xor_sync(0xffffffffu, mx0, 1));
        mx0 = fmaxf(mx0, __shfl_xor_sync(0xffffffffu, mx0, 2));
        mx1 = fmaxf(mx1, __shfl_xor_sync(0xffffffffu, mx1, 1));
        mx1 = fmaxf(mx1, __shfl_xor_sync(0xffffffffu, mx1, 2));

        const float mn0 = fmaxf(m0, mx0), mn1 = fmaxf(m1, mx1);
        const float al0 = ex2f(m0 - mn0), al1 = ex2f(m1 - mn1);
        m0 = mn0; m1 = mn1;

        float sum0 = 0.0f, sum1 = 0.0f;
#pragma unroll
        for (int nt = 0; nt < 8; nt++) {
            s[nt][0] = ex2f(s[nt][0] - mn0); sum0 += s[nt][0];
            s[nt][1] = ex2f(s[nt][1] - mn0); sum0 += s[nt][1];
            s[nt][2] = ex2f(s[nt][2] - mn1); sum1 += s[nt][2];
            s[nt][3] = ex2f(s[nt][3] - mn1); sum1 += s[nt][3];
        }
        sum0 += __shfl_xor_sync(0xffffffffu, sum0, 1);
        sum0 += __shfl_xor_sync(0xffffffffu, sum0, 2);
        sum1 += __shfl_xor_sync(0xffffffffu, sum1, 1);
        sum1 += __shfl_xor_sync(0xffffffffu, sum1, 2);
        l0 = l0 * al0 + sum0;
        l1 = l1 * al1 + sum1;

#pragma unroll
        for (int nt = 0; nt < 8; nt++) {
            O[nt][0] *= al0; O[nt][1] *= al0;
            O[nt][2] *= al1; O[nt][3] *= al1;
        }

        // ---- O += P V: P packed from S fragments IN REGISTERS ----
#pragma unroll
        for (int kc = 0; kc < 4; kc++) {
            uint32_t ph[4], pl[4];
            split_h2(s[2 * kc][0],     s[2 * kc][1],     ph[0], pl[0]);
            split_h2(s[2 * kc][2],     s[2 * kc][3],     ph[1], pl[1]);
            split_h2(s[2 * kc + 1][0], s[2 * kc + 1][1], ph[2], pl[2]);
            split_h2(s[2 * kc + 1][2], s[2 * kc + 1][3], ph[3], pl[3]);
#pragma unroll
            for (int nt = 0; nt < 8; nt++) {
                uint32_t vh[2], vl[2];
                ldsm_x2(va_h + nt * 1152 + kc * 32, vh);
                ldsm_x2(va_l + nt * 1152 + kc * 32, vl);
                mma_f16(O[nt], ph, vh);
                mma_f16(O[nt], pl, vh);
                mma_f16(O[nt], ph, vl);
            }
        }

        if (pf) {
            __syncthreads();
#pragma unroll
            for (int i = 0; i < 4; i++) {
                sts_chunk(SKH, SKL, i, kc4[i]);
                sts_chunk(SVH, SVL, i, vc4[i]);
            }
            __syncthreads();
        }
    }

    // ---- Write UNNORMALIZED partial O + (m,l) per row ----
    const int r0 = q0 + wid * 16 + grp;
    float* op = opart + (size_t)sp * SEQ * EMB;
#pragma unroll
    for (int nt = 0; nt < 8; nt++) {
        const int c = h * HD + nt * 8 + tg * 2;
        *(float2*)&op[(size_t)r0 * EMB + c]       = make_float2(O[nt][0], O[nt][1]);
        *(float2*)&op[(size_t)(r0 + 8) * EMB + c] = make_float2(O[nt][2], O[nt][3]);
    }
    if (tg == 0) {
        float* mlp = ml + (((size_t)sp * HEADS + h) * SEQ) * 2;
        *(float2*)&mlp[(size_t)r0 * 2]       = make_float2(m0, l0);
        *(float2*)&mlp[(size_t)(r0 + 8) * 2] = make_float2(m1, l1);
    }
}

// ---------------------------------------------------------------------------
// Merge the 3 split-K partials; emit ctx as 2 bf16 limb planes.
// ---------------------------------------------------------------------------
__global__ __launch_bounds__(256) void merge_kernel(
    const float* __restrict__ part, const float* __restrict__ ml,
    __nv_bfloat16* __restrict__ ctx16)
{
    const int idx = blockIdx.x * 256 + threadIdx.x;
    const int row = idx / (EMB / 4);
    const int c4  = idx % (EMB / 4);
    const int h   = (c4 * 4) >> 6;

    float m[NSPLIT_K], lv[NSPLIT_K];
#pragma unroll
    for (int p = 0; p < NSPLIT_K; p++) {
        float2 v = *(const float2*)(ml + (((size_t)p * HEADS + h) * SEQ + row) * 2);
        m[p] = v.x; lv[p] = v.y;
    }
    const float M = fmaxf(m[0], fmaxf(m[1], m[2]));
    const float w0 = ex2f(m[0] - M), w1 = ex2f(m[1] - M), w2 = ex2f(m[2] - M);
    const float inv = 1.0f / (lv[0] * w0 + lv[1] * w1 + lv[2] * w2);

    const size_t off = (size_t)row * EMB + c4 * 4;
    float4 a = *(const float4*)(part + off);
    float4 b = *(const float4*)(part + (size_t)SEQ * EMB + off);
    float4 c = *(const float4*)(part + 2 * (size_t)SEQ * EMB + off);
    float4 o;
    o.x = (a.x * w0 + b.x * w1 + c.x * w2) * inv;
    o.y = (a.y * w0 + b.y * w1 + c.y * w2) * inv;
    o.z = (a.z * w0 + b.z * w1 + c.z * w2) * inv;
    o.w = (a.w * w0 + b.w * w1 + c.w * w2) * inv;

    uint32_t h0, m0_, l0_, h1, m1_, l1_;
    split_pair_bf(o.x, o.y, h0, m0_, l0_, false);
    split_pair_bf(o.z, o.w, h1, m1_, l1_, false);
    *(uint2*)(ctx16 + off)                     = make_uint2(h0, h1);
    *(uint2*)(ctx16 + (size_t)SEQ * EMB + off) = make_uint2(m0_, m1_);
}

// ---------------------------------------------------------------------------
extern "C" void kernel_launch(void* const* d_in, const int* in_sizes, int n_in,
                              void* d_out, int out_size)
{
    (void)in_sizes; (void)n_in; (void)out_size;
    const float* x     = (const float*)d_in[0];   // [1,4096,768]
    const float* qkv_w = (const float*)d_in[1];   // [2304,768]
    const float* out_w = (const float*)d_in[2];   // [768,768]
    const float* out_b = (const float*)d_in[3];   // [768]
    float* out = (float*)d_out;                   // [1,4096,768]

    float *qkv = nullptr, *part = nullptr, *ml = nullptr;
    __half *k16 = nullptr, *v16 = nullptr;
    __nv_bfloat16 *w216 = nullptr, *ctx16 = nullptr;
    cudaGetSymbolAddress((void**)&qkv, g_qkv);
    cudaGetSymbolAddress((void**)&k16, g_k16);
    cudaGetSymbolAddress((void**)&v16, g_v16);
    cudaGetSymbolAddress((void**)&part, g_part);
    cudaGetSymbolAddress((void**)&ml, g_ml);
    cudaGetSymbolAddress((void**)&w216, g_w216);
    cudaGetSymbolAddress((void**)&ctx16, g_ctx16);

    // 0) Pre-split out_w only (tiny)
    split_bf_kernel<2><<<(EMB * EMB) / 2048, 256>>>(out_w, w216, (size_t)EMB * EMB);

    // 1) QKV projection (HMMA bf16x3, in-kernel split, BK=64)
    const int smem3 = 6 * LT * (int)sizeof(__nv_bfloat16);   // 110592
    cudaFuncSetAttribute(hmma_gemm_abt<3>,
                         cudaFuncAttributeMaxDynamicSharedMemorySize, smem3);
    hmma_gemm_abt<3><<<dim3(QKV_LD / 128, SEQ / 128), 256, smem3>>>(
        x, qkv_w, nullptr, qkv, SEQ, QKV_LD, EMB);

    // 2) K/V fp16 limb pre-split
    prep_k<<<768, 256>>>(qkv, k16);
    prep_v<<<dim3(64, HEADS), 256>>>(qkv, v16);

    // 3) HMMA flash attention, split-K x3, register-P, ldmatrix loads
    cudaFuncSetAttribute(attn_hmma,
                         cudaFuncAttributeMaxDynamicSharedMemorySize, ATTN_SMEM_BYTES);
    attn_hmma<<<dim3(SEQ / 128, HEADS, NSPLIT_K), 256, ATTN_SMEM_BYTES>>>(
        qkv, k16, v16, part, ml);

    // 4) Merge partials -> ctx bf16 limbs
    merge_kernel<<<(SEQ * EMB / 4) / 256, 256>>>(part, ml, ctx16);

    // 5) Output projection + bias (HMMA bf16x2, pre-split, BK=64)
    const int smem2 = 4 * LT * (int)sizeof(__nv_bfloat16);   // 73728
    cudaFuncSetAttribute(hmma_gemm_pre<2>,
                         cudaFuncAttributeMaxDynamicSharedMemorySize, smem2);
    hmma_gemm_pre<2><<<dim3(EMB / 128, SEQ / 128), 256, smem2>>>(
        ctx16, (size_t)SEQ * EMB, w216, (size_t)EMB * EMB,
        out_b, out, SEQ, EMB, EMB);
}